// round 2
// baseline (speedup 1.0000x reference)
#include <cuda_runtime.h>
#include <math.h>

// Problem dims (fixed)
#define NB   256      // batch
#define TT   128      // timesteps
#define DD   512      // input dim
#define HH   1024     // hidden
#define GG   4096     // 4*H (gates)
#define OUTD 128

// ---------------- device scratch (static, no allocations) ----------------
__device__ float g_Wih_r[GG * DD];   // gate-interleaved W_ih   (16 MB)
__device__ float g_Whh_r[GG * HH];   // gate-interleaved W_hh   (32 MB)
__device__ float g_bias_r[GG];       // b_ih + b_hh, interleaved
__device__ float g_xg[(size_t)NB * TT * GG]; // precomputed input gates (512 MB)
__device__ float g_hbuf0[NB * HH];
__device__ float g_hbuf1[NB * HH];
__device__ float g_cbuf[NB * HH];

// ---------------- prep: reorder weights so gates interleave ----------------
// new row rn = 4*q + p  <->  old row = p*H + q   (p = gate 0..3 = i,f,g,o)
__global__ void prep_kernel(const float* __restrict__ Wih,
                            const float* __restrict__ Whh,
                            const float* __restrict__ bih,
                            const float* __restrict__ bhh) {
    int idx = blockIdx.x * blockDim.x + threadIdx.x;
    int stride = gridDim.x * blockDim.x;
    for (int i = idx; i < GG * DD; i += stride) {
        int rn = i / DD, d = i - rn * DD;
        int q = rn >> 2, p = rn & 3;
        g_Wih_r[i] = Wih[(p * HH + q) * DD + d];
    }
    for (int i = idx; i < GG * HH; i += stride) {
        int rn = i / HH, d = i - rn * HH;
        int q = rn >> 2, p = rn & 3;
        g_Whh_r[i] = Whh[(p * HH + q) * HH + d];
    }
    for (int i = idx; i < GG; i += stride) {
        int q = i >> 2, p = i & 3;
        g_bias_r[i] = bih[p * HH + q] + bhh[p * HH + q];
    }
    for (int i = idx; i < NB * HH; i += stride) {
        g_hbuf0[i] = 0.0f;
        g_cbuf[i]  = 0.0f;
    }
}

// ---------------- generic fp32 GEMM: C = A @ B^T + bias (opt relu) ----------------
// A: [M,K] row-major, B: [N,K] row-major, C: [M,N]
#define EPI_BIAS 0
#define EPI_RELU 1

template <int BM, int BN, int BK, int TM, int TN, int EPI>
__global__ void gemm_bias_kernel(const float* __restrict__ A,
                                 const float* __restrict__ B,
                                 const float* __restrict__ bias,
                                 float* __restrict__ C,
                                 int M, int N, int K) {
    constexpr int NT = (BM * BN) / (TM * TN);
    __shared__ float As[BK][BM];
    __shared__ float Bs[BK][BN];
    const int tid = threadIdx.x;
    const int bn = blockIdx.x, bm = blockIdx.y;
    const int tx = tid % (BN / TN);
    const int ty = tid / (BN / TN);

    const float* Ab = A + (size_t)bm * BM * K;
    const float* Bb = B + (size_t)bn * BN * K;

    float acc[TM][TN];
#pragma unroll
    for (int i = 0; i < TM; i++)
#pragma unroll
        for (int j = 0; j < TN; j++) acc[i][j] = 0.0f;

    for (int k0 = 0; k0 < K; k0 += BK) {
        constexpr int A4 = BM * BK / 4;
        constexpr int B4 = BN * BK / 4;
#pragma unroll
        for (int i0 = 0; i0 < A4; i0 += NT) {
            int i = i0 + tid;
            int r = i / (BK / 4), c = (i % (BK / 4)) * 4;
            float4 v = *reinterpret_cast<const float4*>(Ab + (size_t)r * K + k0 + c);
            As[c + 0][r] = v.x; As[c + 1][r] = v.y;
            As[c + 2][r] = v.z; As[c + 3][r] = v.w;
        }
#pragma unroll
        for (int i0 = 0; i0 < B4; i0 += NT) {
            int i = i0 + tid;
            int r = i / (BK / 4), c = (i % (BK / 4)) * 4;
            float4 v = *reinterpret_cast<const float4*>(Bb + (size_t)r * K + k0 + c);
            Bs[c + 0][r] = v.x; Bs[c + 1][r] = v.y;
            Bs[c + 2][r] = v.z; Bs[c + 3][r] = v.w;
        }
        __syncthreads();
#pragma unroll
        for (int k = 0; k < BK; k++) {
            float ra[TM], rb[TN];
#pragma unroll
            for (int i = 0; i < TM; i += 4) {
                float4 v = *reinterpret_cast<const float4*>(&As[k][ty * TM + i]);
                ra[i] = v.x; ra[i + 1] = v.y; ra[i + 2] = v.z; ra[i + 3] = v.w;
            }
#pragma unroll
            for (int j = 0; j < TN; j += 4) {
                float4 v = *reinterpret_cast<const float4*>(&Bs[k][tx * TN + j]);
                rb[j] = v.x; rb[j + 1] = v.y; rb[j + 2] = v.z; rb[j + 3] = v.w;
            }
#pragma unroll
            for (int i = 0; i < TM; i++)
#pragma unroll
                for (int j = 0; j < TN; j++) acc[i][j] += ra[i] * rb[j];
        }
        __syncthreads();
    }

#pragma unroll
    for (int i = 0; i < TM; i++) {
        int m = bm * BM + ty * TM + i;
#pragma unroll
        for (int j = 0; j < TN; j++) {
            int n = bn * BN + tx * TN + j;
            float v = acc[i][j] + bias[n];
            if (EPI == EPI_RELU) v = fmaxf(v, 0.0f);
            C[(size_t)m * N + n] = v;
        }
    }
}

// ---------------- fused LSTM step: gates GEMM + cell update ----------------
// gates[256,4096] = hprev @ Whh_r^T ; add xg[(m*T+t), :] ; nonlin ; update c,h
// BM=64, BN=128, BK=16, TM=4, TN=8, 256 threads, grid (32, 4) = 128 CTAs
__global__ void lstm_step_kernel(const float* __restrict__ hprev,
                                 float* __restrict__ hnext,
                                 int t) {
    constexpr int BM = 64, BN = 128, BK = 16, TM = 4, TN = 8;
    constexpr int NT = (BM * BN) / (TM * TN);  // 256
    __shared__ float As[BK][BM];
    __shared__ float Bs[BK][BN];
    const int tid = threadIdx.x;
    const int bn = blockIdx.x, bm = blockIdx.y;
    const int tx = tid % (BN / TN);
    const int ty = tid / (BN / TN);

    const float* Ab = hprev + (size_t)bm * BM * HH;
    const float* Bb = g_Whh_r + (size_t)bn * BN * HH;

    float acc[TM][TN];
#pragma unroll
    for (int i = 0; i < TM; i++)
#pragma unroll
        for (int j = 0; j < TN; j++) acc[i][j] = 0.0f;

    for (int k0 = 0; k0 < HH; k0 += BK) {
        constexpr int A4 = BM * BK / 4;   // 256
        constexpr int B4 = BN * BK / 4;   // 512
#pragma unroll
        for (int i0 = 0; i0 < A4; i0 += NT) {
            int i = i0 + tid;
            int r = i / (BK / 4), c = (i % (BK / 4)) * 4;
            float4 v = *reinterpret_cast<const float4*>(Ab + (size_t)r * HH + k0 + c);
            As[c + 0][r] = v.x; As[c + 1][r] = v.y;
            As[c + 2][r] = v.z; As[c + 3][r] = v.w;
        }
#pragma unroll
        for (int i0 = 0; i0 < B4; i0 += NT) {
            int i = i0 + tid;
            int r = i / (BK / 4), c = (i % (BK / 4)) * 4;
            float4 v = *reinterpret_cast<const float4*>(Bb + (size_t)r * HH + k0 + c);
            Bs[c + 0][r] = v.x; Bs[c + 1][r] = v.y;
            Bs[c + 2][r] = v.z; Bs[c + 3][r] = v.w;
        }
        __syncthreads();
#pragma unroll
        for (int k = 0; k < BK; k++) {
            float ra[TM], rb[TN];
            {
                float4 v = *reinterpret_cast<const float4*>(&As[k][ty * TM]);
                ra[0] = v.x; ra[1] = v.y; ra[2] = v.z; ra[3] = v.w;
            }
#pragma unroll
            for (int j = 0; j < TN; j += 4) {
                float4 v = *reinterpret_cast<const float4*>(&Bs[k][tx * TN + j]);
                rb[j] = v.x; rb[j + 1] = v.y; rb[j + 2] = v.z; rb[j + 3] = v.w;
            }
#pragma unroll
            for (int i = 0; i < TM; i++)
#pragma unroll
                for (int j = 0; j < TN; j++) acc[i][j] += ra[i] * rb[j];
        }
        __syncthreads();
    }

    // Epilogue: columns are gate-interleaved (4q+p). Each thread owns 2 full
    // quads per row -> complete i,f,g,o -> do cell update in place.
    const int n0 = bn * BN + tx * TN;   // multiple of 8 -> quad-aligned
#pragma unroll
    for (int i = 0; i < TM; i++) {
        int m = bm * BM + ty * TM + i;
        const float* xr = g_xg + ((size_t)m * TT + t) * GG + n0;
#pragma unroll
        for (int h2 = 0; h2 < TN / 4; h2++) {
            float a0 = acc[i][h2 * 4 + 0] + xr[h2 * 4 + 0];  // i
            float a1 = acc[i][h2 * 4 + 1] + xr[h2 * 4 + 1];  // f
            float a2 = acc[i][h2 * 4 + 2] + xr[h2 * 4 + 2];  // g
            float a3 = acc[i][h2 * 4 + 3] + xr[h2 * 4 + 3];  // o
            float ig = 1.0f / (1.0f + expf(-a0));
            float fg = 1.0f / (1.0f + expf(-a1));
            float gg = tanhf(a2);
            float og = 1.0f / (1.0f + expf(-a3));
            int q = n0 / 4 + h2;
            float cn = fg * g_cbuf[m * HH + q] + ig * gg;
            g_cbuf[m * HH + q] = cn;
            hnext[m * HH + q] = og * tanhf(cn);
        }
    }
}

// ---------------- host side ----------------
extern "C" void kernel_launch(void* const* d_in, const int* in_sizes, int n_in,
                              void* d_out, int out_size) {
    const float* x    = (const float*)d_in[0];
    const float* W_ih = (const float*)d_in[1];
    const float* W_hh = (const float*)d_in[2];
    const float* b_ih = (const float*)d_in[3];
    const float* b_hh = (const float*)d_in[4];
    const float* W1   = (const float*)d_in[5];
    const float* b1   = (const float*)d_in[6];
    const float* W2   = (const float*)d_in[7];
    const float* b2   = (const float*)d_in[8];
    float* out = (float*)d_out;

    float *p_Wih_r, *p_bias_r, *p_xg, *p_h0, *p_h1;
    cudaGetSymbolAddress((void**)&p_Wih_r,  g_Wih_r);
    cudaGetSymbolAddress((void**)&p_bias_r, g_bias_r);
    cudaGetSymbolAddress((void**)&p_xg,     g_xg);
    cudaGetSymbolAddress((void**)&p_h0,     g_hbuf0);
    cudaGetSymbolAddress((void**)&p_h1,     g_hbuf1);

    // 1) reorder weights + zero state
    prep_kernel<<<1024, 256>>>(W_ih, W_hh, b_ih, b_hh);

    // 2) x_gates = x @ W_ih_r^T + (b_ih+b_hh)   [32768 x 4096]
    gemm_bias_kernel<128, 128, 16, 8, 8, EPI_BIAS>
        <<<dim3(GG / 128, (NB * TT) / 128), 256>>>(
            x, p_Wih_r, p_bias_r, p_xg, NB * TT, GG, DD);

    // 3) 128 recurrent steps, fused GEMM + cell update, double-buffered h
    float* hb[2] = {p_h0, p_h1};
    for (int t = 0; t < TT; t++) {
        lstm_step_kernel<<<dim3(GG / 128, NB / 64), 256>>>(hb[t & 1], hb[(t + 1) & 1], t);
    }
    float* hlast = hb[TT & 1];  // == p_h0

    // 4) head: pre = relu(h @ W1^T + b1) -> d_out[32768:], out = pre @ W2^T + b2 -> d_out[:32768]
    float* pre_out = out + NB * OUTD;
    gemm_bias_kernel<64, 128, 16, 4, 8, EPI_RELU>
        <<<dim3(HH / 128, NB / 64), 256>>>(hlast, W1, b1, pre_out, NB, HH, HH);
    gemm_bias_kernel<64, 128, 16, 4, 8, EPI_BIAS>
        <<<dim3(OUTD / 128, NB / 64), 256>>>(pre_out, W2, b2, out, NB, OUTD, HH);
}

// round 4
// speedup vs baseline: 2.5665x; 2.5665x over previous
#include <cuda_runtime.h>
#include <cuda_bf16.h>
#include <math.h>
#include <stdint.h>

// Problem dims (fixed)
#define NB   256
#define TT   128
#define DD   512
#define HH   1024
#define GG   4096
#define OUTD 128

typedef __nv_bfloat16 bf16;

// ---------------- device scratch ----------------
__device__ bf16 g_Wih_hi[GG * DD];
__device__ bf16 g_Wih_lo[GG * DD];
__device__ bf16 g_Whh_hi[GG * HH];
__device__ bf16 g_Whh_lo[GG * HH];
__device__ bf16 g_x_hi[(size_t)NB * TT * DD];
__device__ bf16 g_x_lo[(size_t)NB * TT * DD];
__device__ float g_bias_r[GG];
__device__ float g_xg[(size_t)NB * TT * GG];
__device__ bf16 g_h_hi[2][NB * HH];
__device__ bf16 g_h_lo[2][NB * HH];
__device__ float g_hlast[NB * HH];
__device__ float g_cbuf[NB * HH];

// ---------------- low-level helpers (base sm_80+ feature set only) ----------------
__device__ __forceinline__ uint32_t smem_u32(const void* p) {
    uint32_t a;
    asm("{ .reg .u64 t; cvta.to.shared.u64 t, %1; cvt.u32.u64 %0, t; }" : "=r"(a) : "l"(p));
    return a;
}
__device__ __forceinline__ void cp16(uint32_t dst, const void* src) {
    asm volatile("cp.async.cg.shared.global [%0], [%1], 16;"
                 :: "r"(dst), "l"(__cvta_generic_to_global(src)) : "memory");
}
#define CP_COMMIT() asm volatile("cp.async.commit_group;" ::: "memory")
#define CP_WAIT(n)  asm volatile("cp.async.wait_group %0;" :: "n"(n) : "memory")

__device__ __forceinline__ void ldsm4(uint32_t* r, uint32_t addr) {
    asm volatile("ldmatrix.sync.aligned.m8n8.x4.shared.b16 {%0,%1,%2,%3}, [%4];"
                 : "=r"(r[0]), "=r"(r[1]), "=r"(r[2]), "=r"(r[3]) : "r"(addr));
}
__device__ __forceinline__ void mma16816(float* d, const uint32_t* a, uint32_t b0, uint32_t b1) {
    asm volatile(
        "mma.sync.aligned.m16n8k16.row.col.f32.bf16.bf16.f32 "
        "{%0,%1,%2,%3}, {%4,%5,%6,%7}, {%8,%9}, {%0,%1,%2,%3};"
        : "+f"(d[0]), "+f"(d[1]), "+f"(d[2]), "+f"(d[3])
        : "r"(a[0]), "r"(a[1]), "r"(a[2]), "r"(a[3]), "r"(b0), "r"(b1));
}

// smem tile layout: rows of 32 bf16 (64B = 4 x 16B chunks), chunk XOR-swizzled
__device__ __forceinline__ uint32_t swz(int row, int j) {
    return (uint32_t)(row * 64 + ((j ^ ((row >> 1) & 3)) << 4));
}

// ---------------- prep: reorder/convert weights, split x into hi/lo ----------------
__global__ void prep_kernel(const float* __restrict__ x,
                            const float* __restrict__ Wih,
                            const float* __restrict__ Whh,
                            const float* __restrict__ bih,
                            const float* __restrict__ bhh) {
    int idx = blockIdx.x * blockDim.x + threadIdx.x;
    int stride = gridDim.x * blockDim.x;
    for (int i = idx; i < GG * DD; i += stride) {
        int rn = i / DD, d = i - rn * DD;
        int q = rn >> 2, p = rn & 3;
        float w = Wih[(p * HH + q) * DD + d];
        bf16 hi = __float2bfloat16(w);
        g_Wih_hi[i] = hi;
        g_Wih_lo[i] = __float2bfloat16(w - __bfloat162float(hi));
    }
    for (int i = idx; i < GG * HH; i += stride) {
        int rn = i / HH, d = i - rn * HH;
        int q = rn >> 2, p = rn & 3;
        float w = Whh[(p * HH + q) * HH + d];
        bf16 hi = __float2bfloat16(w);
        g_Whh_hi[i] = hi;
        g_Whh_lo[i] = __float2bfloat16(w - __bfloat162float(hi));
    }
    for (size_t i = idx; i < (size_t)NB * TT * DD; i += stride) {
        float v = x[i];
        bf16 hi = __float2bfloat16(v);
        g_x_hi[i] = hi;
        g_x_lo[i] = __float2bfloat16(v - __bfloat162float(hi));
    }
    for (int i = idx; i < GG; i += stride) {
        int q = i >> 2, p = i & 3;
        g_bias_r[i] = bih[p * HH + q] + bhh[p * HH + q];
    }
    for (int i = idx; i < NB * HH; i += stride) {
        g_h_hi[0][i] = __float2bfloat16(0.0f);
        g_h_lo[0][i] = __float2bfloat16(0.0f);
        g_cbuf[i] = 0.0f;
    }
}

// ---------------- shared HMMA mainloop ----------------
// C_tile[BM x 128] = sum over 3 passes (Ahi*Bhi, Ahi*Blo, Alo*Bhi) of A[m0..][K] @ B[n0..][K]^T
// 8 warps as 2(M) x 4(N); warp tile (BM/2) x 32; BK=32; double-buffered cp.async.
template <int BM, int MF>
__device__ __forceinline__ void mma_mainloop(
    const bf16* __restrict__ Ahi, const bf16* __restrict__ Alo,
    const bf16* __restrict__ Bhi, const bf16* __restrict__ Blo,
    int K, int m0, int n0, uint32_t sbase, float acc[MF][4][4]) {
    const int tid = threadIdx.x;
    const int lane = tid & 31, wid = tid >> 5;
    const int wm = (wid >> 2) * (BM / 2);
    const int wn = (wid & 3) * 32;
    constexpr int AT = BM * 64;          // A tile bytes
    constexpr int BT = 128 * 64;         // B tile bytes
    const int KC = K / 32;
    const int NC = 3 * KC;

    auto load_chunk = [&](int ci, int buf) {
        int pass = ci / KC, kc = ci - pass * KC;
        const bf16* Ag = (pass < 2) ? Ahi : Alo;
        const bf16* Bg = (pass == 1) ? Blo : Bhi;
        uint32_t base = sbase + buf * (AT + BT);
#pragma unroll
        for (int i0 = 0; i0 < BM * 4; i0 += 256) {
            int i = i0 + tid;
            int row = i >> 2, j = i & 3;
            cp16(base + swz(row, j), Ag + (size_t)(m0 + row) * K + kc * 32 + j * 8);
        }
#pragma unroll
        for (int i0 = 0; i0 < 512; i0 += 256) {
            int i = i0 + tid;
            int row = i >> 2, j = i & 3;
            cp16(base + AT + swz(row, j), Bg + (size_t)(n0 + row) * K + kc * 32 + j * 8);
        }
        CP_COMMIT();
    };

    load_chunk(0, 0);
    for (int ci = 0; ci < NC; ci++) {
        int buf = ci & 1;
        if (ci + 1 < NC) { load_chunk(ci + 1, buf ^ 1); CP_WAIT(1); }
        else             { CP_WAIT(0); }
        __syncthreads();
        uint32_t sA = sbase + buf * (AT + BT);
        uint32_t sB = sA + AT;
#pragma unroll
        for (int ks = 0; ks < 2; ks++) {
            uint32_t a[MF][4], br[2][4];
#pragma unroll
            for (int mi = 0; mi < MF; mi++) {
                int row = wm + mi * 16 + (lane & 7) + ((lane >> 3) & 1) * 8;
                int j = ks * 2 + (lane >> 4);
                ldsm4(a[mi], sA + swz(row, j));
            }
#pragma unroll
            for (int bi = 0; bi < 2; bi++) {
                int row = wn + bi * 16 + (lane & 7) + ((lane >> 3) & 1) * 8;
                int j = ks * 2 + (lane >> 4);
                ldsm4(br[bi], sB + swz(row, j));
            }
#pragma unroll
            for (int mi = 0; mi < MF; mi++)
#pragma unroll
                for (int nf = 0; nf < 4; nf++)
                    mma16816(acc[mi][nf], a[mi], br[nf >> 1][nf & 1], br[nf >> 1][(nf & 1) + 2]);
        }
        __syncthreads();
    }
}

// ---------------- xgates: g_xg = x @ Wih^T + bias via HMMA ----------------
__global__ __launch_bounds__(256, 1)
void xgates_mma_kernel() {
    __shared__ __align__(1024) char smem[32768];
    const uint32_t sbase = smem_u32(smem);
    const int bn = blockIdx.x, bm = blockIdx.y;
    const int tid = threadIdx.x, lane = tid & 31, wid = tid >> 5;
    const int wm = (wid >> 2) * 64, wn = (wid & 3) * 32;

    float acc[4][4][4];
#pragma unroll
    for (int i = 0; i < 4; i++)
#pragma unroll
        for (int j = 0; j < 4; j++)
#pragma unroll
            for (int k = 0; k < 4; k++) acc[i][j][k] = 0.0f;

    mma_mainloop<128, 4>(g_x_hi, g_x_lo, g_Wih_hi, g_Wih_lo, DD,
                         bm * 128, bn * 128, sbase, acc);

#pragma unroll
    for (int mi = 0; mi < 4; mi++) {
#pragma unroll
        for (int nf = 0; nf < 4; nf++) {
            int m = bm * 128 + wm + mi * 16 + lane / 4;
            int n = bn * 128 + wn + nf * 8 + 2 * (lane & 3);
            float2 b2 = *reinterpret_cast<const float2*>(&g_bias_r[n]);
            *reinterpret_cast<float2*>(&g_xg[(size_t)m * GG + n]) =
                make_float2(acc[mi][nf][0] + b2.x, acc[mi][nf][1] + b2.y);
            *reinterpret_cast<float2*>(&g_xg[(size_t)(m + 8) * GG + n]) =
                make_float2(acc[mi][nf][2] + b2.x, acc[mi][nf][3] + b2.y);
        }
    }
}

// ---------------- fused LSTM step via HMMA ----------------
__global__ __launch_bounds__(256, 1)
void lstm_step_mma(const bf16* __restrict__ h_hi, const bf16* __restrict__ h_lo,
                   bf16* __restrict__ hn_hi, bf16* __restrict__ hn_lo, int t) {
    __shared__ __align__(1024) char smem[32768];
    const uint32_t sbase = smem_u32(smem);
    const int bn = blockIdx.x, bm = blockIdx.y;
    const int tid = threadIdx.x, lane = tid & 31, wid = tid >> 5;
    const int wm = (wid >> 2) * 32, wn = (wid & 3) * 32;

    float acc[2][4][4];
#pragma unroll
    for (int i = 0; i < 2; i++)
#pragma unroll
        for (int j = 0; j < 4; j++)
#pragma unroll
            for (int k = 0; k < 4; k++) acc[i][j][k] = 0.0f;

    mma_mainloop<64, 2>(h_hi, h_lo, g_Whh_hi, g_Whh_lo, HH,
                        bm * 64, bn * 128, sbase, acc);

    // stage gates in smem (reuse tile buffers; mainloop's trailing sync protects)
    float* gsm = reinterpret_cast<float*>(smem);
#pragma unroll
    for (int mi = 0; mi < 2; mi++) {
#pragma unroll
        for (int nf = 0; nf < 4; nf++) {
            int r0 = wm + mi * 16 + lane / 4;
            int col = wn + nf * 8 + 2 * (lane & 3);
            *reinterpret_cast<float2*>(&gsm[r0 * 128 + col]) =
                make_float2(acc[mi][nf][0], acc[mi][nf][1]);
            *reinterpret_cast<float2*>(&gsm[(r0 + 8) * 128 + col]) =
                make_float2(acc[mi][nf][2], acc[mi][nf][3]);
        }
    }
    __syncthreads();

    // cell update: 64 rows x 32 quads = 2048 cells, 8 per thread
#pragma unroll
    for (int it = 0; it < 8; it++) {
        int idx = it * 256 + tid;
        int m = idx >> 5, q = idx & 31;
        int mg = bm * 64 + m;
        int qg = bn * 32 + q;
        float4 gv = *reinterpret_cast<const float4*>(&gsm[m * 128 + q * 4]);
        const float* xr = g_xg + ((size_t)mg * TT + t) * GG + bn * 128 + q * 4;
        float4 xv = *reinterpret_cast<const float4*>(xr);
        float a0 = gv.x + xv.x;
        float a1 = gv.y + xv.y;
        float a2 = gv.z + xv.z;
        float a3 = gv.w + xv.w;
        float ig = 1.0f / (1.0f + expf(-a0));
        float fg = 1.0f / (1.0f + expf(-a1));
        float gg = tanhf(a2);
        float og = 1.0f / (1.0f + expf(-a3));
        float cn = fg * g_cbuf[mg * HH + qg] + ig * gg;
        g_cbuf[mg * HH + qg] = cn;
        float hv = og * tanhf(cn);
        g_hlast[mg * HH + qg] = hv;
        bf16 hi = __float2bfloat16(hv);
        hn_hi[(size_t)mg * HH + qg] = hi;
        hn_lo[(size_t)mg * HH + qg] = __float2bfloat16(hv - __bfloat162float(hi));
    }
}

// ---------------- fp32 SIMT GEMM (head only) ----------------
#define EPI_BIAS 0
#define EPI_RELU 1
template <int BM, int BN, int BK, int TM, int TN, int EPI>
__global__ void gemm_bias_kernel(const float* __restrict__ A,
                                 const float* __restrict__ B,
                                 const float* __restrict__ bias,
                                 float* __restrict__ C,
                                 int M, int N, int K) {
    constexpr int NT = (BM * BN) / (TM * TN);
    __shared__ float As[BK][BM];
    __shared__ float Bs[BK][BN];
    const int tid = threadIdx.x;
    const int bn = blockIdx.x, bm = blockIdx.y;
    const int tx = tid % (BN / TN);
    const int ty = tid / (BN / TN);
    const float* Ab = A + (size_t)bm * BM * K;
    const float* Bb = B + (size_t)bn * BN * K;
    float acc[TM][TN];
#pragma unroll
    for (int i = 0; i < TM; i++)
#pragma unroll
        for (int j = 0; j < TN; j++) acc[i][j] = 0.0f;
    for (int k0 = 0; k0 < K; k0 += BK) {
        constexpr int A4 = BM * BK / 4;
        constexpr int B4 = BN * BK / 4;
#pragma unroll
        for (int i0 = 0; i0 < A4; i0 += NT) {
            int i = i0 + tid;
            int r = i / (BK / 4), c = (i % (BK / 4)) * 4;
            float4 v = *reinterpret_cast<const float4*>(Ab + (size_t)r * K + k0 + c);
            As[c + 0][r] = v.x; As[c + 1][r] = v.y; As[c + 2][r] = v.z; As[c + 3][r] = v.w;
        }
#pragma unroll
        for (int i0 = 0; i0 < B4; i0 += NT) {
            int i = i0 + tid;
            int r = i / (BK / 4), c = (i % (BK / 4)) * 4;
            float4 v = *reinterpret_cast<const float4*>(Bb + (size_t)r * K + k0 + c);
            Bs[c + 0][r] = v.x; Bs[c + 1][r] = v.y; Bs[c + 2][r] = v.z; Bs[c + 3][r] = v.w;
        }
        __syncthreads();
#pragma unroll
        for (int k = 0; k < BK; k++) {
            float ra[TM], rb[TN];
#pragma unroll
            for (int i = 0; i < TM; i += 4) {
                float4 v = *reinterpret_cast<const float4*>(&As[k][ty * TM + i]);
                ra[i] = v.x; ra[i + 1] = v.y; ra[i + 2] = v.z; ra[i + 3] = v.w;
            }
#pragma unroll
            for (int j = 0; j < TN; j += 4) {
                float4 v = *reinterpret_cast<const float4*>(&Bs[k][tx * TN + j]);
                rb[j] = v.x; rb[j + 1] = v.y; rb[j + 2] = v.z; rb[j + 3] = v.w;
            }
#pragma unroll
            for (int i = 0; i < TM; i++)
#pragma unroll
                for (int j = 0; j < TN; j++) acc[i][j] += ra[i] * rb[j];
        }
        __syncthreads();
    }
#pragma unroll
    for (int i = 0; i < TM; i++) {
        int m = bm * BM + ty * TM + i;
#pragma unroll
        for (int j = 0; j < TN; j++) {
            int n = bn * BN + tx * TN + j;
            float v = acc[i][j] + bias[n];
            if (EPI == EPI_RELU) v = fmaxf(v, 0.0f);
            C[(size_t)m * N + n] = v;
        }
    }
}

// ---------------- host ----------------
extern "C" void kernel_launch(void* const* d_in, const int* in_sizes, int n_in,
                              void* d_out, int out_size) {
    const float* x    = (const float*)d_in[0];
    const float* W_ih = (const float*)d_in[1];
    const float* W_hh = (const float*)d_in[2];
    const float* b_ih = (const float*)d_in[3];
    const float* b_hh = (const float*)d_in[4];
    const float* W1   = (const float*)d_in[5];
    const float* b1   = (const float*)d_in[6];
    const float* W2   = (const float*)d_in[7];
    const float* b2   = (const float*)d_in[8];
    float* out = (float*)d_out;

    float* p_hlast;
    bf16 *p_hhi[2], *p_hlo[2];
    cudaGetSymbolAddress((void**)&p_hlast, g_hlast);
    {
        bf16* base;
        cudaGetSymbolAddress((void**)&base, g_h_hi);
        p_hhi[0] = base; p_hhi[1] = base + NB * HH;
        cudaGetSymbolAddress((void**)&base, g_h_lo);
        p_hlo[0] = base; p_hlo[1] = base + NB * HH;
    }

    // 1) reorder + hi/lo split weights and x; zero state
    prep_kernel<<<1024, 256>>>(x, W_ih, W_hh, b_ih, b_hh);

    // 2) x_gates via HMMA (bn fast-varying -> W_ih tiles stay L2-resident)
    xgates_mma_kernel<<<dim3(GG / 128, (NB * TT) / 128), 256>>>();

    // 3) 128 recurrent steps via HMMA, fused cell update
    for (int t = 0; t < TT; t++) {
        int a = t & 1, b = (t + 1) & 1;
        lstm_step_mma<<<dim3(GG / 128, NB / 64), 256>>>(
            p_hhi[a], p_hlo[a], p_hhi[b], p_hlo[b], t);
    }

    // 4) head (fp32 SIMT)
    float* pre_out = out + NB * OUTD;
    gemm_bias_kernel<64, 128, 16, 4, 8, EPI_RELU>
        <<<dim3(HH / 128, NB / 64), 256>>>(p_hlast, W1, b1, pre_out, NB, HH, HH);
    gemm_bias_kernel<64, 128, 16, 4, 8, EPI_BIAS>
        <<<dim3(OUTD / 128, NB / 64), 256>>>(pre_out, W2, b2, out, NB, OUTD, HH);
}

// round 5
// speedup vs baseline: 3.2212x; 1.2551x over previous
#include <cuda_runtime.h>
#include <cuda_bf16.h>
#include <math.h>
#include <stdint.h>

// Problem dims (fixed)
#define NB   256
#define TT   128
#define DD   512
#define HH   1024
#define GG   4096
#define OUTD 128

typedef __nv_bfloat16 bf16;

// ---------------- device scratch ----------------
__device__ bf16 g_Wih_hi[GG * DD];
__device__ bf16 g_Wih_lo[GG * DD];
__device__ bf16 g_Whh_hi[GG * HH];
__device__ bf16 g_Whh_lo[GG * HH];
__device__ bf16 g_x_hi[(size_t)NB * TT * DD];
__device__ bf16 g_x_lo[(size_t)NB * TT * DD];
__device__ float g_bias_r[GG];
__device__ float g_xg[(size_t)TT * NB * GG];   // TRANSPOSED: [t][batch][gate]
__device__ bf16 g_h_hi[2][NB * HH];
__device__ bf16 g_h_lo[2][NB * HH];
__device__ float g_hlast[NB * HH];
__device__ float g_cbuf[NB * HH];

// ---------------- low-level helpers ----------------
__device__ __forceinline__ uint32_t smem_u32(const void* p) {
    uint32_t a;
    asm("{ .reg .u64 t; cvta.to.shared.u64 t, %1; cvt.u32.u64 %0, t; }" : "=r"(a) : "l"(p));
    return a;
}
__device__ __forceinline__ void cp16(uint32_t dst, const void* src) {
    asm volatile("cp.async.cg.shared.global [%0], [%1], 16;"
                 :: "r"(dst), "l"(__cvta_generic_to_global(src)) : "memory");
}
#define CP_COMMIT() asm volatile("cp.async.commit_group;" ::: "memory")
#define CP_WAIT(n)  asm volatile("cp.async.wait_group %0;" :: "n"(n) : "memory")

__device__ __forceinline__ void ldsm4(uint32_t* r, uint32_t addr) {
    asm volatile("ldmatrix.sync.aligned.m8n8.x4.shared.b16 {%0,%1,%2,%3}, [%4];"
                 : "=r"(r[0]), "=r"(r[1]), "=r"(r[2]), "=r"(r[3]) : "r"(addr));
}
__device__ __forceinline__ void mma16816(float* d, const uint32_t* a, uint32_t b0, uint32_t b1) {
    asm volatile(
        "mma.sync.aligned.m16n8k16.row.col.f32.bf16.bf16.f32 "
        "{%0,%1,%2,%3}, {%4,%5,%6,%7}, {%8,%9}, {%0,%1,%2,%3};"
        : "+f"(d[0]), "+f"(d[1]), "+f"(d[2]), "+f"(d[3])
        : "r"(a[0]), "r"(a[1]), "r"(a[2]), "r"(a[3]), "r"(b0), "r"(b1));
}

// tile rows = 64 bf16 = 128B = 8 x 16B chunks; 8-way XOR swizzle within the row
__device__ __forceinline__ uint32_t swz(int row, int j) {
    return (uint32_t)(row * 128 + ((j ^ (row & 7)) << 4));
}

// ---------------- prep ----------------
__global__ void prep_kernel(const float* __restrict__ x,
                            const float* __restrict__ Wih,
                            const float* __restrict__ Whh,
                            const float* __restrict__ bih,
                            const float* __restrict__ bhh) {
    int idx = blockIdx.x * blockDim.x + threadIdx.x;
    int stride = gridDim.x * blockDim.x;
    for (int i = idx; i < GG * DD; i += stride) {
        int rn = i / DD, d = i - rn * DD;
        int q = rn >> 2, p = rn & 3;
        float w = Wih[(p * HH + q) * DD + d];
        bf16 hi = __float2bfloat16(w);
        g_Wih_hi[i] = hi;
        g_Wih_lo[i] = __float2bfloat16(w - __bfloat162float(hi));
    }
    for (int i = idx; i < GG * HH; i += stride) {
        int rn = i / HH, d = i - rn * HH;
        int q = rn >> 2, p = rn & 3;
        float w = Whh[(p * HH + q) * HH + d];
        bf16 hi = __float2bfloat16(w);
        g_Whh_hi[i] = hi;
        g_Whh_lo[i] = __float2bfloat16(w - __bfloat162float(hi));
    }
    for (size_t i = idx; i < (size_t)NB * TT * DD; i += stride) {
        float v = x[i];
        bf16 hi = __float2bfloat16(v);
        g_x_hi[i] = hi;
        g_x_lo[i] = __float2bfloat16(v - __bfloat162float(hi));
    }
    for (int i = idx; i < GG; i += stride) {
        int q = i >> 2, p = i & 3;
        g_bias_r[i] = bih[p * HH + q] + bhh[p * HH + q];
    }
    for (int i = idx; i < NB * HH; i += stride) {
        g_h_hi[0][i] = __float2bfloat16(0.0f);
        g_h_lo[0][i] = __float2bfloat16(0.0f);
        g_cbuf[i] = 0.0f;
    }
}

// ---------------- multistage HMMA mainloop ----------------
// C[BM x 128] = sum of 3 passes (Ahi*Bhi, Ahi*Blo, Alo*Bhi); BK=64, S=4 stages.
// 8 warps 2(M) x 4(N); warp tile (BM/2) x 32.
template <int BM, int MF>
__device__ __forceinline__ void mma_mainloop(
    const bf16* __restrict__ Ahi, const bf16* __restrict__ Alo,
    const bf16* __restrict__ Bhi, const bf16* __restrict__ Blo,
    int K, int m0, int n0, uint32_t sbase, float acc[MF][4][4]) {
    constexpr int S = 4;
    constexpr int AT = BM * 128;          // A stage bytes (BM rows x 128B)
    constexpr int BT = 128 * 128;         // B stage bytes
    constexpr int STAGE = AT + BT;
    const int tid = threadIdx.x;
    const int lane = tid & 31, wid = tid >> 5;
    const int wm = (wid >> 2) * (BM / 2);
    const int wn = (wid & 3) * 32;
    const int KC = K / 64;
    const int NC = 3 * KC;

    auto load_chunk = [&](int ci, int buf) {
        int pass = ci / KC, kc = ci - pass * KC;
        const bf16* Ag = (pass < 2) ? Ahi : Alo;
        const bf16* Bg = (pass == 1) ? Blo : Bhi;
        uint32_t base = sbase + buf * STAGE;
#pragma unroll
        for (int i0 = 0; i0 < BM * 8; i0 += 256) {
            int i = i0 + tid;
            int row = i >> 3, j = i & 7;
            cp16(base + swz(row, j), Ag + (size_t)(m0 + row) * K + kc * 64 + j * 8);
        }
#pragma unroll
        for (int i0 = 0; i0 < 1024; i0 += 256) {
            int i = i0 + tid;
            int row = i >> 3, j = i & 7;
            cp16(base + AT + swz(row, j), Bg + (size_t)(n0 + row) * K + kc * 64 + j * 8);
        }
        CP_COMMIT();
    };

    // prologue: stages 0..S-2  (any cp.async issued by caller joins group 0)
    load_chunk(0, 0);
    load_chunk(1, 1);
    load_chunk(2, 2);

    for (int ci = 0; ci < NC; ci++) {
        int buf = ci & (S - 1);
        CP_WAIT(S - 2);
        __syncthreads();
        if (ci + S - 1 < NC) load_chunk(ci + S - 1, (ci + S - 1) & (S - 1));
        else CP_COMMIT();   // keep group accounting uniform
        uint32_t sA = sbase + buf * STAGE;
        uint32_t sB = sA + AT;
#pragma unroll
        for (int ks = 0; ks < 4; ks++) {
            uint32_t a[MF][4], br[2][4];
#pragma unroll
            for (int mi = 0; mi < MF; mi++) {
                int row = wm + mi * 16 + (lane & 15);
                int j = ks * 2 + (lane >> 4);
                ldsm4(a[mi], sA + swz(row, j));
            }
#pragma unroll
            for (int bi = 0; bi < 2; bi++) {
                int row = wn + bi * 16 + (lane & 15);
                int j = ks * 2 + (lane >> 4);
                ldsm4(br[bi], sB + swz(row, j));
            }
#pragma unroll
            for (int mi = 0; mi < MF; mi++)
#pragma unroll
                for (int nf = 0; nf < 4; nf++)
                    mma16816(acc[mi][nf], a[mi], br[nf >> 1][nf & 1], br[nf >> 1][(nf & 1) + 2]);
        }
    }
    __syncthreads();   // protect stage buffers before epilogue reuse
}

// ---------------- xgates: writes transposed g_xg[t][batch][gate] ----------------
__global__ __launch_bounds__(256, 1)
void xgates_mma_kernel() {
    extern __shared__ __align__(1024) char smem[];
    const uint32_t sbase = smem_u32(smem);
    const int bn = blockIdx.x, bm = blockIdx.y;
    const int tid = threadIdx.x, lane = tid & 31, wid = tid >> 5;
    const int wm = (wid >> 2) * 64, wn = (wid & 3) * 32;

    float acc[4][4][4];
#pragma unroll
    for (int i = 0; i < 4; i++)
#pragma unroll
        for (int j = 0; j < 4; j++)
#pragma unroll
            for (int k = 0; k < 4; k++) acc[i][j][k] = 0.0f;

    mma_mainloop<128, 4>(g_x_hi, g_x_lo, g_Wih_hi, g_Wih_lo, DD,
                         bm * 128, bn * 128, sbase, acc);

#pragma unroll
    for (int mi = 0; mi < 4; mi++) {
#pragma unroll
        for (int nf = 0; nf < 4; nf++) {
            int m = bm * 128 + wm + mi * 16 + lane / 4;   // token index
            int n = bn * 128 + wn + nf * 8 + 2 * (lane & 3);
            float2 b2 = *reinterpret_cast<const float2*>(&g_bias_r[n]);
            int t0 = m % TT, b0 = m / TT;
            int m8 = m + 8;
            int t1 = m8 % TT, b1 = m8 / TT;
            *reinterpret_cast<float2*>(&g_xg[((size_t)t0 * NB + b0) * GG + n]) =
                make_float2(acc[mi][nf][0] + b2.x, acc[mi][nf][1] + b2.y);
            *reinterpret_cast<float2*>(&g_xg[((size_t)t1 * NB + b1) * GG + n]) =
                make_float2(acc[mi][nf][2] + b2.x, acc[mi][nf][3] + b2.y);
        }
    }
}

// ---------------- fused LSTM step ----------------
// smem: 4 stages x 24KB = 96KB pipeline, then 32KB xg prefetch = 128KB
#define STEP_STAGE   (64 * 128 + 128 * 128)
#define STEP_XG_OFF  (4 * STEP_STAGE)
#define STEP_SMEM    (STEP_XG_OFF + 64 * 128 * 4)

__global__ __launch_bounds__(256, 1)
void lstm_step_mma(const bf16* __restrict__ h_hi, const bf16* __restrict__ h_lo,
                   bf16* __restrict__ hn_hi, bf16* __restrict__ hn_lo, int t) {
    extern __shared__ __align__(1024) char smem[];
    const uint32_t sbase = smem_u32(smem);
    const int bn = blockIdx.x, bm = blockIdx.y;
    const int tid = threadIdx.x, lane = tid & 31, wid = tid >> 5;
    const int wm = (wid >> 2) * 32, wn = (wid & 3) * 32;

    // prefetch this tile's x-gates [64 rows x 128 cols f32] (joins cp group 0)
    {
        const float* xgsrc = g_xg + ((size_t)t * NB + bm * 64) * GG + bn * 128;
#pragma unroll
        for (int s = 0; s < 8; s++) {
            int i = tid + s * 256;
            int row = i >> 5, j = i & 31;
            cp16(sbase + STEP_XG_OFF + row * 512 + j * 16, xgsrc + (size_t)row * GG + j * 4);
        }
    }

    float acc[2][4][4];
#pragma unroll
    for (int i = 0; i < 2; i++)
#pragma unroll
        for (int j = 0; j < 4; j++)
#pragma unroll
            for (int k = 0; k < 4; k++) acc[i][j][k] = 0.0f;

    mma_mainloop<64, 2>(h_hi, h_lo, g_Whh_hi, g_Whh_lo, HH,
                        bm * 64, bn * 128, sbase, acc);

    // stage gates in smem (pipeline buffers are free now)
    float* gsm = reinterpret_cast<float*>(smem);
#pragma unroll
    for (int mi = 0; mi < 2; mi++) {
#pragma unroll
        for (int nf = 0; nf < 4; nf++) {
            int r0 = wm + mi * 16 + lane / 4;
            int col = wn + nf * 8 + 2 * (lane & 3);
            *reinterpret_cast<float2*>(&gsm[r0 * 128 + col]) =
                make_float2(acc[mi][nf][0], acc[mi][nf][1]);
            *reinterpret_cast<float2*>(&gsm[(r0 + 8) * 128 + col]) =
                make_float2(acc[mi][nf][2], acc[mi][nf][3]);
        }
    }
    __syncthreads();

    const float* xgsm = reinterpret_cast<const float*>(smem + STEP_XG_OFF);
#pragma unroll
    for (int it = 0; it < 8; it++) {
        int idx = it * 256 + tid;
        int m = idx >> 5, q = idx & 31;
        int mg = bm * 64 + m;
        int qg = bn * 32 + q;
        float4 gv = *reinterpret_cast<const float4*>(&gsm[m * 128 + q * 4]);
        float4 xv = *reinterpret_cast<const float4*>(&xgsm[m * 128 + q * 4]);
        float a0 = gv.x + xv.x;
        float a1 = gv.y + xv.y;
        float a2 = gv.z + xv.z;
        float a3 = gv.w + xv.w;
        float ig = 1.0f / (1.0f + expf(-a0));
        float fg = 1.0f / (1.0f + expf(-a1));
        float gg = tanhf(a2);
        float og = 1.0f / (1.0f + expf(-a3));
        float cn = fg * g_cbuf[mg * HH + qg] + ig * gg;
        g_cbuf[mg * HH + qg] = cn;
        float hv = og * tanhf(cn);
        g_hlast[mg * HH + qg] = hv;
        bf16 hi = __float2bfloat16(hv);
        hn_hi[(size_t)mg * HH + qg] = hi;
        hn_lo[(size_t)mg * HH + qg] = __float2bfloat16(hv - __bfloat162float(hi));
    }
}

// ---------------- fp32 SIMT GEMM (head only) ----------------
#define EPI_BIAS 0
#define EPI_RELU 1
template <int BM, int BN, int BK, int TM, int TN, int EPI>
__global__ void gemm_bias_kernel(const float* __restrict__ A,
                                 const float* __restrict__ B,
                                 const float* __restrict__ bias,
                                 float* __restrict__ C,
                                 int M, int N, int K) {
    constexpr int NT = (BM * BN) / (TM * TN);
    __shared__ float As[BK][BM];
    __shared__ float Bs[BK][BN];
    const int tid = threadIdx.x;
    const int bn = blockIdx.x, bm = blockIdx.y;
    const int tx = tid % (BN / TN);
    const int ty = tid / (BN / TN);
    const float* Ab = A + (size_t)bm * BM * K;
    const float* Bb = B + (size_t)bn * BN * K;
    float acc[TM][TN];
#pragma unroll
    for (int i = 0; i < TM; i++)
#pragma unroll
        for (int j = 0; j < TN; j++) acc[i][j] = 0.0f;
    for (int k0 = 0; k0 < K; k0 += BK) {
        constexpr int A4 = BM * BK / 4;
        constexpr int B4 = BN * BK / 4;
#pragma unroll
        for (int i0 = 0; i0 < A4; i0 += NT) {
            int i = i0 + tid;
            int r = i / (BK / 4), c = (i % (BK / 4)) * 4;
            float4 v = *reinterpret_cast<const float4*>(Ab + (size_t)r * K + k0 + c);
            As[c + 0][r] = v.x; As[c + 1][r] = v.y; As[c + 2][r] = v.z; As[c + 3][r] = v.w;
        }
#pragma unroll
        for (int i0 = 0; i0 < B4; i0 += NT) {
            int i = i0 + tid;
            int r = i / (BK / 4), c = (i % (BK / 4)) * 4;
            float4 v = *reinterpret_cast<const float4*>(Bb + (size_t)r * K + k0 + c);
            Bs[c + 0][r] = v.x; Bs[c + 1][r] = v.y; Bs[c + 2][r] = v.z; Bs[c + 3][r] = v.w;
        }
        __syncthreads();
#pragma unroll
        for (int k = 0; k < BK; k++) {
            float ra[TM], rb[TN];
#pragma unroll
            for (int i = 0; i < TM; i += 4) {
                float4 v = *reinterpret_cast<const float4*>(&As[k][ty * TM + i]);
                ra[i] = v.x; ra[i + 1] = v.y; ra[i + 2] = v.z; ra[i + 3] = v.w;
            }
#pragma unroll
            for (int j = 0; j < TN; j += 4) {
                float4 v = *reinterpret_cast<const float4*>(&Bs[k][tx * TN + j]);
                rb[j] = v.x; rb[j + 1] = v.y; rb[j + 2] = v.z; rb[j + 3] = v.w;
            }
#pragma unroll
            for (int i = 0; i < TM; i++)
#pragma unroll
                for (int j = 0; j < TN; j++) acc[i][j] += ra[i] * rb[j];
        }
        __syncthreads();
    }
#pragma unroll
    for (int i = 0; i < TM; i++) {
        int m = bm * BM + ty * TM + i;
#pragma unroll
        for (int j = 0; j < TN; j++) {
            int n = bn * BN + tx * TN + j;
            float v = acc[i][j] + bias[n];
            if (EPI == EPI_RELU) v = fmaxf(v, 0.0f);
            C[(size_t)m * N + n] = v;
        }
    }
}

// ---------------- host ----------------
extern "C" void kernel_launch(void* const* d_in, const int* in_sizes, int n_in,
                              void* d_out, int out_size) {
    const float* x    = (const float*)d_in[0];
    const float* W_ih = (const float*)d_in[1];
    const float* W_hh = (const float*)d_in[2];
    const float* b_ih = (const float*)d_in[3];
    const float* b_hh = (const float*)d_in[4];
    const float* W1   = (const float*)d_in[5];
    const float* b1   = (const float*)d_in[6];
    const float* W2   = (const float*)d_in[7];
    const float* b2   = (const float*)d_in[8];
    float* out = (float*)d_out;

    float* p_hlast;
    bf16 *p_hhi[2], *p_hlo[2];
    cudaGetSymbolAddress((void**)&p_hlast, g_hlast);
    {
        bf16* base;
        cudaGetSymbolAddress((void**)&base, g_h_hi);
        p_hhi[0] = base; p_hhi[1] = base + NB * HH;
        cudaGetSymbolAddress((void**)&base, g_h_lo);
        p_hlo[0] = base; p_hlo[1] = base + NB * HH;
    }

    static int attr_set = 0;
    const int XG_SMEM = 4 * (128 * 128 + 128 * 128);   // 128KB
    if (!attr_set) {
        cudaFuncSetAttribute(lstm_step_mma, cudaFuncAttributeMaxDynamicSharedMemorySize, STEP_SMEM);
        cudaFuncSetAttribute(xgates_mma_kernel, cudaFuncAttributeMaxDynamicSharedMemorySize, XG_SMEM);
        attr_set = 1;
    }

    // 1) reorder + hi/lo split weights and x; zero state
    prep_kernel<<<1024, 256>>>(x, W_ih, W_hh, b_ih, b_hh);

    // 2) x_gates via HMMA, written transposed [t][batch][gate]
    xgates_mma_kernel<<<dim3(GG / 128, (NB * TT) / 128), 256, XG_SMEM>>>();

    // 3) 128 recurrent steps via HMMA, fused cell update
    for (int t = 0; t < TT; t++) {
        int a = t & 1, b = (t + 1) & 1;
        lstm_step_mma<<<dim3(GG / 128, NB / 64), 256, STEP_SMEM>>>(
            p_hhi[a], p_hlo[a], p_hhi[b], p_hlo[b], t);
    }

    // 4) head (fp32 SIMT)
    float* pre_out = out + NB * OUTD;
    gemm_bias_kernel<64, 128, 16, 4, 8, EPI_RELU>
        <<<dim3(HH / 128, NB / 64), 256>>>(p_hlast, W1, b1, pre_out, NB, HH, HH);
    gemm_bias_kernel<64, 128, 16, 4, 8, EPI_BIAS>
        <<<dim3(OUTD / 128, NB / 64), 256>>>(pre_out, W2, b2, out, NB, OUTD, HH);
}

// round 6
// speedup vs baseline: 3.3744x; 1.0475x over previous
#include <cuda_runtime.h>
#include <cuda_bf16.h>
#include <math.h>
#include <stdint.h>

// Problem dims (fixed)
#define NB   256
#define TT   128
#define DD   512
#define HH   1024
#define GG   4096
#define OUTD 128

typedef __nv_bfloat16 bf16;

// ---------------- device scratch ----------------
__device__ bf16 g_Wih_hi[GG * DD];
__device__ bf16 g_Wih_lo[GG * DD];
__device__ bf16 g_Whh_hi[GG * HH];
__device__ bf16 g_Whh_lo[GG * HH];
__device__ bf16 g_x_hi[(size_t)NB * TT * DD];
__device__ bf16 g_x_lo[(size_t)NB * TT * DD];
__device__ float g_bias_r[GG];
__device__ float g_xg[(size_t)TT * NB * GG];   // [t][batch][gate]
__device__ bf16 g_h_hi[2][NB * HH];
__device__ bf16 g_h_lo[2][NB * HH];
__device__ float g_hlast[NB * HH];
__device__ float g_cbuf[NB * HH];

// ---------------- low-level helpers ----------------
__device__ __forceinline__ uint32_t smem_u32(const void* p) {
    uint32_t a;
    asm("{ .reg .u64 t; cvta.to.shared.u64 t, %1; cvt.u32.u64 %0, t; }" : "=r"(a) : "l"(p));
    return a;
}
__device__ __forceinline__ void cp16(uint32_t dst, const void* src) {
    asm volatile("cp.async.cg.shared.global [%0], [%1], 16;"
                 :: "r"(dst), "l"(__cvta_generic_to_global(src)) : "memory");
}
#define CP_COMMIT() asm volatile("cp.async.commit_group;" ::: "memory")
#define CP_WAIT(n)  asm volatile("cp.async.wait_group %0;" :: "n"(n) : "memory")

__device__ __forceinline__ void ldsm4(uint32_t* r, uint32_t addr) {
    asm volatile("ldmatrix.sync.aligned.m8n8.x4.shared.b16 {%0,%1,%2,%3}, [%4];"
                 : "=r"(r[0]), "=r"(r[1]), "=r"(r[2]), "=r"(r[3]) : "r"(addr));
}
__device__ __forceinline__ void mma16816(float* d, const uint32_t* a, uint32_t b0, uint32_t b1) {
    asm volatile(
        "mma.sync.aligned.m16n8k16.row.col.f32.bf16.bf16.f32 "
        "{%0,%1,%2,%3}, {%4,%5,%6,%7}, {%8,%9}, {%0,%1,%2,%3};"
        : "+f"(d[0]), "+f"(d[1]), "+f"(d[2]), "+f"(d[3])
        : "r"(a[0]), "r"(a[1]), "r"(a[2]), "r"(a[3]), "r"(b0), "r"(b1));
}

// tile rows = 64 bf16 = 128B = 8 x 16B chunks; 8-way XOR swizzle within the row
__device__ __forceinline__ uint32_t swz(int row, int j) {
    return (uint32_t)(row * 128 + ((j ^ (row & 7)) << 4));
}

// ---------------- prep ----------------
__global__ void prep_kernel(const float* __restrict__ x,
                            const float* __restrict__ Wih,
                            const float* __restrict__ Whh,
                            const float* __restrict__ bih,
                            const float* __restrict__ bhh) {
    int idx = blockIdx.x * blockDim.x + threadIdx.x;
    int stride = gridDim.x * blockDim.x;
    for (int i = idx; i < GG * DD; i += stride) {
        int rn = i / DD, d = i - rn * DD;
        int q = rn >> 2, p = rn & 3;
        float w = Wih[(p * HH + q) * DD + d];
        bf16 hi = __float2bfloat16(w);
        g_Wih_hi[i] = hi;
        g_Wih_lo[i] = __float2bfloat16(w - __bfloat162float(hi));
    }
    for (int i = idx; i < GG * HH; i += stride) {
        int rn = i / HH, d = i - rn * HH;
        int q = rn >> 2, p = rn & 3;
        float w = Whh[(p * HH + q) * HH + d];
        bf16 hi = __float2bfloat16(w);
        g_Whh_hi[i] = hi;
        g_Whh_lo[i] = __float2bfloat16(w - __bfloat162float(hi));
    }
    for (size_t i = idx; i < (size_t)NB * TT * DD; i += stride) {
        float v = x[i];
        bf16 hi = __float2bfloat16(v);
        g_x_hi[i] = hi;
        g_x_lo[i] = __float2bfloat16(v - __bfloat162float(hi));
    }
    for (int i = idx; i < GG; i += stride) {
        int q = i >> 2, p = i & 3;
        g_bias_r[i] = bih[p * HH + q] + bhh[p * HH + q];
    }
    for (int i = idx; i < NB * HH; i += stride) {
        g_h_hi[0][i] = __float2bfloat16(0.0f);
        g_h_lo[0][i] = __float2bfloat16(0.0f);
        g_cbuf[i] = 0.0f;
    }
}

// ---------------- multistage HMMA mainloop ----------------
// C[BM x 128] = 3 passes (Ahi*Bhi, Ahi*Blo, Alo*Bhi); BK=64, S stages.
// 8 warps 2(M) x 4(N); warp tile (BM/2) x 32. MF = BM/32.
template <int BM, int MF, int S>
__device__ __forceinline__ void mma_mainloop(
    const bf16* __restrict__ Ahi, const bf16* __restrict__ Alo,
    const bf16* __restrict__ Bhi, const bf16* __restrict__ Blo,
    int K, int m0, int n0, uint32_t sbase, float acc[MF][4][4]) {
    constexpr int AT = BM * 128;
    constexpr int BT = 128 * 128;
    constexpr int STAGE = AT + BT;
    const int tid = threadIdx.x;
    const int lane = tid & 31, wid = tid >> 5;
    const int wm = (wid >> 2) * (BM / 2);
    const int wn = (wid & 3) * 32;
    const int KC = K / 64;
    const int NC = 3 * KC;

    auto load_chunk = [&](int ci, int buf) {
        int pass = ci / KC, kc = ci - pass * KC;
        const bf16* Ag = (pass < 2) ? Ahi : Alo;
        const bf16* Bg = (pass == 1) ? Blo : Bhi;
        uint32_t base = sbase + buf * STAGE;
#pragma unroll
        for (int i0 = 0; i0 < BM * 8; i0 += 256) {
            int i = i0 + tid;
            int row = i >> 3, j = i & 7;
            cp16(base + swz(row, j), Ag + (size_t)(m0 + row) * K + kc * 64 + j * 8);
        }
#pragma unroll
        for (int i0 = 0; i0 < 1024; i0 += 256) {
            int i = i0 + tid;
            int row = i >> 3, j = i & 7;
            cp16(base + AT + swz(row, j), Bg + (size_t)(n0 + row) * K + kc * 64 + j * 8);
        }
        CP_COMMIT();
    };

    // prologue: stages 0..S-2 (caller's earlier cp.async joins group 0)
#pragma unroll
    for (int s = 0; s < S - 1; s++) load_chunk(s, s);

    int cbuf = 0;                 // stage being computed
    int lbuf = (S - 1) % S;       // stage being loaded
    for (int ci = 0; ci < NC; ci++) {
        CP_WAIT(S - 2);
        __syncthreads();
        if (ci + S - 1 < NC) load_chunk(ci + S - 1, lbuf);
        else CP_COMMIT();
        lbuf = (lbuf + 1 == S) ? 0 : lbuf + 1;
        uint32_t sA = sbase + cbuf * STAGE;
        uint32_t sB = sA + AT;
        cbuf = (cbuf + 1 == S) ? 0 : cbuf + 1;
#pragma unroll
        for (int ks = 0; ks < 4; ks++) {
            uint32_t a[MF][4], br[2][4];
#pragma unroll
            for (int mi = 0; mi < MF; mi++) {
                int row = wm + mi * 16 + (lane & 15);
                int j = ks * 2 + (lane >> 4);
                ldsm4(a[mi], sA + swz(row, j));
            }
#pragma unroll
            for (int bi = 0; bi < 2; bi++) {
                int row = wn + bi * 16 + (lane & 15);
                int j = ks * 2 + (lane >> 4);
                ldsm4(br[bi], sB + swz(row, j));
            }
#pragma unroll
            for (int mi = 0; mi < MF; mi++)
#pragma unroll
                for (int nf = 0; nf < 4; nf++)
                    mma16816(acc[mi][nf], a[mi], br[nf >> 1][nf & 1], br[nf >> 1][(nf & 1) + 2]);
        }
    }
    __syncthreads();   // protect stage buffers before epilogue reuse
}

// ---------------- xgates: writes transposed g_xg[t][batch][gate] ----------------
__global__ __launch_bounds__(256, 1)
void xgates_mma_kernel() {
    extern __shared__ __align__(1024) char smem[];
    const uint32_t sbase = smem_u32(smem);
    const int bn = blockIdx.x, bm = blockIdx.y;
    const int tid = threadIdx.x, lane = tid & 31, wid = tid >> 5;
    const int wm = (wid >> 2) * 64, wn = (wid & 3) * 32;

    float acc[4][4][4];
#pragma unroll
    for (int i = 0; i < 4; i++)
#pragma unroll
        for (int j = 0; j < 4; j++)
#pragma unroll
            for (int k = 0; k < 4; k++) acc[i][j][k] = 0.0f;

    mma_mainloop<128, 4, 3>(g_x_hi, g_x_lo, g_Wih_hi, g_Wih_lo, DD,
                            bm * 128, bn * 128, sbase, acc);

#pragma unroll
    for (int mi = 0; mi < 4; mi++) {
#pragma unroll
        for (int nf = 0; nf < 4; nf++) {
            int m = bm * 128 + wm + mi * 16 + lane / 4;
            int n = bn * 128 + wn + nf * 8 + 2 * (lane & 3);
            float2 b2 = *reinterpret_cast<const float2*>(&g_bias_r[n]);
            int t0 = m % TT, b0 = m / TT;
            int m8 = m + 8;
            int t1 = m8 % TT, b1 = m8 / TT;
            *reinterpret_cast<float2*>(&g_xg[((size_t)t0 * NB + b0) * GG + n]) =
                make_float2(acc[mi][nf][0] + b2.x, acc[mi][nf][1] + b2.y);
            *reinterpret_cast<float2*>(&g_xg[((size_t)t1 * NB + b1) * GG + n]) =
                make_float2(acc[mi][nf][2] + b2.x, acc[mi][nf][3] + b2.y);
        }
    }
}

// ---------------- fused LSTM step ----------------
// BM=32: grid (32, 8) = 256 CTAs -> 2 per SM. smem: 3 x 20KB + 16KB xg = 76KB
#define STEP_BM      32
#define STEP_STAGE   (STEP_BM * 128 + 128 * 128)
#define STEP_XG_OFF  (3 * STEP_STAGE)
#define STEP_SMEM    (STEP_XG_OFF + STEP_BM * 128 * 4)

__global__ __launch_bounds__(256, 2)
void lstm_step_mma(const bf16* __restrict__ h_hi, const bf16* __restrict__ h_lo,
                   bf16* __restrict__ hn_hi, bf16* __restrict__ hn_lo, int t) {
    extern __shared__ __align__(1024) char smem[];
    const uint32_t sbase = smem_u32(smem);
    const int bn = blockIdx.x, bm = blockIdx.y;
    const int tid = threadIdx.x, lane = tid & 31, wid = tid >> 5;
    const int wm = (wid >> 2) * 16, wn = (wid & 3) * 32;

    // prefetch this tile's x-gates [32 rows x 128 cols f32] (joins cp group 0)
    {
        const float* xgsrc = g_xg + ((size_t)t * NB + bm * STEP_BM) * GG + bn * 128;
#pragma unroll
        for (int s = 0; s < 4; s++) {
            int i = tid + s * 256;
            int row = i >> 5, j = i & 31;
            cp16(sbase + STEP_XG_OFF + row * 512 + j * 16, xgsrc + (size_t)row * GG + j * 4);
        }
    }

    float acc[1][4][4];
#pragma unroll
    for (int j = 0; j < 4; j++)
#pragma unroll
        for (int k = 0; k < 4; k++) acc[0][j][k] = 0.0f;

    mma_mainloop<STEP_BM, 1, 3>(h_hi, h_lo, g_Whh_hi, g_Whh_lo, HH,
                                bm * STEP_BM, bn * 128, sbase, acc);

    // stage gates in smem (pipeline buffers free after mainloop's trailing sync)
    float* gsm = reinterpret_cast<float*>(smem);
#pragma unroll
    for (int nf = 0; nf < 4; nf++) {
        int r0 = wm + lane / 4;
        int col = wn + nf * 8 + 2 * (lane & 3);
        *reinterpret_cast<float2*>(&gsm[r0 * 128 + col]) =
            make_float2(acc[0][nf][0], acc[0][nf][1]);
        *reinterpret_cast<float2*>(&gsm[(r0 + 8) * 128 + col]) =
            make_float2(acc[0][nf][2], acc[0][nf][3]);
    }
    __syncthreads();

    const float* xgsm = reinterpret_cast<const float*>(smem + STEP_XG_OFF);
#pragma unroll
    for (int it = 0; it < 4; it++) {
        int idx = it * 256 + tid;
        int m = idx >> 5, q = idx & 31;
        int mg = bm * STEP_BM + m;
        int qg = bn * 32 + q;
        float4 gv = *reinterpret_cast<const float4*>(&gsm[m * 128 + q * 4]);
        float4 xv = *reinterpret_cast<const float4*>(&xgsm[m * 128 + q * 4]);
        float a0 = gv.x + xv.x;
        float a1 = gv.y + xv.y;
        float a2 = gv.z + xv.z;
        float a3 = gv.w + xv.w;
        float ig = 1.0f / (1.0f + expf(-a0));
        float fg = 1.0f / (1.0f + expf(-a1));
        float gg = tanhf(a2);
        float og = 1.0f / (1.0f + expf(-a3));
        float cn = fg * g_cbuf[mg * HH + qg] + ig * gg;
        g_cbuf[mg * HH + qg] = cn;
        float hv = og * tanhf(cn);
        g_hlast[mg * HH + qg] = hv;
        bf16 hi = __float2bfloat16(hv);
        hn_hi[(size_t)mg * HH + qg] = hi;
        hn_lo[(size_t)mg * HH + qg] = __float2bfloat16(hv - __bfloat162float(hi));
    }
}

// ---------------- fp32 SIMT GEMM (head only) ----------------
#define EPI_BIAS 0
#define EPI_RELU 1
template <int BM, int BN, int BK, int TM, int TN, int EPI>
__global__ void gemm_bias_kernel(const float* __restrict__ A,
                                 const float* __restrict__ B,
                                 const float* __restrict__ bias,
                                 float* __restrict__ C,
                                 int M, int N, int K) {
    constexpr int NT = (BM * BN) / (TM * TN);
    __shared__ float As[BK][BM];
    __shared__ float Bs[BK][BN];
    const int tid = threadIdx.x;
    const int bn = blockIdx.x, bm = blockIdx.y;
    const int tx = tid % (BN / TN);
    const int ty = tid / (BN / TN);
    const float* Ab = A + (size_t)bm * BM * K;
    const float* Bb = B + (size_t)bn * BN * K;
    float acc[TM][TN];
#pragma unroll
    for (int i = 0; i < TM; i++)
#pragma unroll
        for (int j = 0; j < TN; j++) acc[i][j] = 0.0f;
    for (int k0 = 0; k0 < K; k0 += BK) {
        constexpr int A4 = BM * BK / 4;
        constexpr int B4 = BN * BK / 4;
#pragma unroll
        for (int i0 = 0; i0 < A4; i0 += NT) {
            int i = i0 + tid;
            int r = i / (BK / 4), c = (i % (BK / 4)) * 4;
            float4 v = *reinterpret_cast<const float4*>(Ab + (size_t)r * K + k0 + c);
            As[c + 0][r] = v.x; As[c + 1][r] = v.y; As[c + 2][r] = v.z; As[c + 3][r] = v.w;
        }
#pragma unroll
        for (int i0 = 0; i0 < B4; i0 += NT) {
            int i = i0 + tid;
            int r = i / (BK / 4), c = (i % (BK / 4)) * 4;
            float4 v = *reinterpret_cast<const float4*>(Bb + (size_t)r * K + k0 + c);
            Bs[c + 0][r] = v.x; Bs[c + 1][r] = v.y; Bs[c + 2][r] = v.z; Bs[c + 3][r] = v.w;
        }
        __syncthreads();
#pragma unroll
        for (int k = 0; k < BK; k++) {
            float ra[TM], rb[TN];
#pragma unroll
            for (int i = 0; i < TM; i += 4) {
                float4 v = *reinterpret_cast<const float4*>(&As[k][ty * TM + i]);
                ra[i] = v.x; ra[i + 1] = v.y; ra[i + 2] = v.z; ra[i + 3] = v.w;
            }
#pragma unroll
            for (int j = 0; j < TN; j += 4) {
                float4 v = *reinterpret_cast<const float4*>(&Bs[k][tx * TN + j]);
                rb[j] = v.x; rb[j + 1] = v.y; rb[j + 2] = v.z; rb[j + 3] = v.w;
            }
#pragma unroll
            for (int i = 0; i < TM; i++)
#pragma unroll
                for (int j = 0; j < TN; j++) acc[i][j] += ra[i] * rb[j];
        }
        __syncthreads();
    }
#pragma unroll
    for (int i = 0; i < TM; i++) {
        int m = bm * BM + ty * TM + i;
#pragma unroll
        for (int j = 0; j < TN; j++) {
            int n = bn * BN + tx * TN + j;
            float v = acc[i][j] + bias[n];
            if (EPI == EPI_RELU) v = fmaxf(v, 0.0f);
            C[(size_t)m * N + n] = v;
        }
    }
}

// ---------------- host ----------------
extern "C" void kernel_launch(void* const* d_in, const int* in_sizes, int n_in,
                              void* d_out, int out_size) {
    const float* x    = (const float*)d_in[0];
    const float* W_ih = (const float*)d_in[1];
    const float* W_hh = (const float*)d_in[2];
    const float* b_ih = (const float*)d_in[3];
    const float* b_hh = (const float*)d_in[4];
    const float* W1   = (const float*)d_in[5];
    const float* b1   = (const float*)d_in[6];
    const float* W2   = (const float*)d_in[7];
    const float* b2   = (const float*)d_in[8];
    float* out = (float*)d_out;

    float* p_hlast;
    bf16 *p_hhi[2], *p_hlo[2];
    cudaGetSymbolAddress((void**)&p_hlast, g_hlast);
    {
        bf16* base;
        cudaGetSymbolAddress((void**)&base, g_h_hi);
        p_hhi[0] = base; p_hhi[1] = base + NB * HH;
        cudaGetSymbolAddress((void**)&base, g_h_lo);
        p_hlo[0] = base; p_hlo[1] = base + NB * HH;
    }

    static int attr_set = 0;
    const int XG_SMEM = 3 * (128 * 128 + 128 * 128);   // 96KB
    if (!attr_set) {
        cudaFuncSetAttribute(lstm_step_mma, cudaFuncAttributeMaxDynamicSharedMemorySize, STEP_SMEM);
        cudaFuncSetAttribute(xgates_mma_kernel, cudaFuncAttributeMaxDynamicSharedMemorySize, XG_SMEM);
        attr_set = 1;
    }

    // 1) reorder + hi/lo split weights and x; zero state
    prep_kernel<<<1024, 256>>>(x, W_ih, W_hh, b_ih, b_hh);

    // 2) x_gates via HMMA, written transposed [t][batch][gate]
    xgates_mma_kernel<<<dim3(GG / 128, (NB * TT) / 128), 256, XG_SMEM>>>();

    // 3) 128 recurrent steps via HMMA, fused cell update (256 CTAs -> 2/SM)
    for (int t = 0; t < TT; t++) {
        int a = t & 1, b = (t + 1) & 1;
        lstm_step_mma<<<dim3(GG / 128, NB / STEP_BM), 256, STEP_SMEM>>>(
            p_hhi[a], p_hlo[a], p_hhi[b], p_hlo[b], t);
    }

    // 4) head (fp32 SIMT)
    float* pre_out = out + NB * OUTD;
    gemm_bias_kernel<64, 128, 16, 4, 8, EPI_RELU>
        <<<dim3(HH / 128, NB / 64), 256>>>(p_hlast, W1, b1, pre_out, NB, HH, HH);
    gemm_bias_kernel<64, 128, 16, 4, 8, EPI_BIAS>
        <<<dim3(OUTD / 128, NB / 64), 256>>>(pre_out, W2, b2, out, NB, OUTD, HH);
}

// round 7
// speedup vs baseline: 3.7226x; 1.1032x over previous
#include <cuda_runtime.h>
#include <cuda_bf16.h>
#include <math.h>
#include <stdint.h>

// Problem dims (fixed)
#define NB   256
#define TT   128
#define DD   512
#define HH   1024
#define GG   4096
#define OUTD 128

typedef __nv_bfloat16 bf16;

// ---------------- device scratch ----------------
__device__ bf16 g_Wih_hi[GG * DD];
__device__ bf16 g_Wih_lo[GG * DD];
__device__ bf16 g_Whh_hi[GG * HH];
__device__ bf16 g_Whh_lo[GG * HH];
__device__ bf16 g_x_hi[(size_t)NB * TT * DD];
__device__ bf16 g_x_lo[(size_t)NB * TT * DD];
__device__ float g_bias_r[GG];
__device__ float g_xg[(size_t)TT * NB * GG];   // [t][batch][gate]
__device__ bf16 g_h_hi[2][NB * HH];
__device__ bf16 g_h_lo[2][NB * HH];
__device__ float g_hlast[NB * HH];
__device__ float g_cbuf[NB * HH];

// ---------------- low-level helpers ----------------
__device__ __forceinline__ uint32_t smem_u32(const void* p) {
    uint32_t a;
    asm("{ .reg .u64 t; cvta.to.shared.u64 t, %1; cvt.u32.u64 %0, t; }" : "=r"(a) : "l"(p));
    return a;
}
__device__ __forceinline__ void cp16(uint32_t dst, const void* src) {
    asm volatile("cp.async.cg.shared.global [%0], [%1], 16;"
                 :: "r"(dst), "l"(__cvta_generic_to_global(src)) : "memory");
}
#define CP_COMMIT() asm volatile("cp.async.commit_group;" ::: "memory")
#define CP_WAIT(n)  asm volatile("cp.async.wait_group %0;" :: "n"(n) : "memory")

__device__ __forceinline__ void ldsm4(uint32_t* r, uint32_t addr) {
    asm volatile("ldmatrix.sync.aligned.m8n8.x4.shared.b16 {%0,%1,%2,%3}, [%4];"
                 : "=r"(r[0]), "=r"(r[1]), "=r"(r[2]), "=r"(r[3]) : "r"(addr));
}
__device__ __forceinline__ void mma16816(float* d, const uint32_t* a, uint32_t b0, uint32_t b1) {
    asm volatile(
        "mma.sync.aligned.m16n8k16.row.col.f32.bf16.bf16.f32 "
        "{%0,%1,%2,%3}, {%4,%5,%6,%7}, {%8,%9}, {%0,%1,%2,%3};"
        : "+f"(d[0]), "+f"(d[1]), "+f"(d[2]), "+f"(d[3])
        : "r"(a[0]), "r"(a[1]), "r"(a[2]), "r"(a[3]), "r"(b0), "r"(b1));
}

// tile rows = 64 bf16 = 128B = 8 x 16B chunks; 8-way XOR swizzle within the row
__device__ __forceinline__ uint32_t swz(int row, int j) {
    return (uint32_t)(row * 128 + ((j ^ (row & 7)) << 4));
}

// ---------------- prep ----------------
__global__ void prep_kernel(const float* __restrict__ x,
                            const float* __restrict__ Wih,
                            const float* __restrict__ Whh,
                            const float* __restrict__ bih,
                            const float* __restrict__ bhh) {
    int idx = blockIdx.x * blockDim.x + threadIdx.x;
    int stride = gridDim.x * blockDim.x;
    for (int i = idx; i < GG * DD; i += stride) {
        int rn = i / DD, d = i - rn * DD;
        int q = rn >> 2, p = rn & 3;
        float w = Wih[(p * HH + q) * DD + d];
        bf16 hi = __float2bfloat16(w);
        g_Wih_hi[i] = hi;
        g_Wih_lo[i] = __float2bfloat16(w - __bfloat162float(hi));
    }
    for (int i = idx; i < GG * HH; i += stride) {
        int rn = i / HH, d = i - rn * HH;
        int q = rn >> 2, p = rn & 3;
        float w = Whh[(p * HH + q) * HH + d];
        bf16 hi = __float2bfloat16(w);
        g_Whh_hi[i] = hi;
        g_Whh_lo[i] = __float2bfloat16(w - __bfloat162float(hi));
    }
    for (size_t i = idx; i < (size_t)NB * TT * DD; i += stride) {
        float v = x[i];
        bf16 hi = __float2bfloat16(v);
        g_x_hi[i] = hi;
        g_x_lo[i] = __float2bfloat16(v - __bfloat162float(hi));
    }
    for (int i = idx; i < GG; i += stride) {
        int q = i >> 2, p = i & 3;
        g_bias_r[i] = bih[p * HH + q] + bhh[p * HH + q];
    }
    for (int i = idx; i < NB * HH; i += stride) {
        g_h_hi[0][i] = __float2bfloat16(0.0f);
        g_h_lo[0][i] = __float2bfloat16(0.0f);
        g_cbuf[i] = 0.0f;
    }
}

// ---------------- combined-pass multistage HMMA mainloop ----------------
// Per K-chunk (BK=64) load Ahi, Alo, Bhi, Blo ONCE; issue 3 MMA passes
// (hi*hi, hi*lo, lo*hi) reusing register fragments. 8 warps 2(M) x 4(N);
// warp tile (BM/2) x 32; MF = BM/32. S pipeline stages.
template <int BM, int MF, int S>
__device__ __forceinline__ void mma_mainloop(
    const bf16* __restrict__ Ahi, const bf16* __restrict__ Alo,
    const bf16* __restrict__ Bhi, const bf16* __restrict__ Blo,
    int K, int m0, int n0, uint32_t sbase, float acc[MF][4][4]) {
    constexpr int ATILE = BM * 128;          // one A tensor per stage
    constexpr int BTILE = 128 * 128;         // one B tensor per stage
    constexpr int STAGE = 2 * ATILE + 2 * BTILE;
    const int tid = threadIdx.x;
    const int lane = tid & 31, wid = tid >> 5;
    const int wm = (wid >> 2) * (BM / 2);
    const int wn = (wid & 3) * 32;
    const int KC = K / 64;

    auto load_chunk = [&](int kc, int buf) {
        uint32_t base = sbase + buf * STAGE;
#pragma unroll
        for (int i0 = 0; i0 < BM * 8; i0 += 256) {
            int i = i0 + tid;
            int row = i >> 3, j = i & 7;
            size_t goff = (size_t)(m0 + row) * K + kc * 64 + j * 8;
            uint32_t so = swz(row, j);
            cp16(base + so, Ahi + goff);
            cp16(base + ATILE + so, Alo + goff);
        }
#pragma unroll
        for (int i0 = 0; i0 < 1024; i0 += 256) {
            int i = i0 + tid;
            int row = i >> 3, j = i & 7;
            size_t goff = (size_t)(n0 + row) * K + kc * 64 + j * 8;
            uint32_t so = swz(row, j);
            cp16(base + 2 * ATILE + so, Bhi + goff);
            cp16(base + 2 * ATILE + BTILE + so, Blo + goff);
        }
        CP_COMMIT();
    };

    // prologue: stages 0..S-2 (caller's earlier cp.async joins group 0)
#pragma unroll
    for (int s = 0; s < S - 1; s++) load_chunk(s, s);

    int cbuf = 0;
    int lbuf = (S - 1) % S;
    for (int ci = 0; ci < KC; ci++) {
        CP_WAIT(S - 2);
        __syncthreads();
        if (ci + S - 1 < KC) load_chunk(ci + S - 1, lbuf);
        else CP_COMMIT();
        lbuf = (lbuf + 1 == S) ? 0 : lbuf + 1;
        uint32_t sAh = sbase + cbuf * STAGE;
        uint32_t sAl = sAh + ATILE;
        uint32_t sBh = sAh + 2 * ATILE;
        uint32_t sBl = sBh + BTILE;
        cbuf = (cbuf + 1 == S) ? 0 : cbuf + 1;
#pragma unroll
        for (int ks = 0; ks < 4; ks++) {
            uint32_t ah[MF][4], al[MF][4], bh[2][4], bl[2][4];
            const int j = ks * 2 + (lane >> 4);
#pragma unroll
            for (int mi = 0; mi < MF; mi++) {
                int row = wm + mi * 16 + (lane & 15);
                uint32_t so = swz(row, j);
                ldsm4(ah[mi], sAh + so);
                ldsm4(al[mi], sAl + so);
            }
#pragma unroll
            for (int bi = 0; bi < 2; bi++) {
                int row = wn + bi * 16 + (lane & 15);
                uint32_t so = swz(row, j);
                ldsm4(bh[bi], sBh + so);
                ldsm4(bl[bi], sBl + so);
            }
            // pass 0: Ahi * Bhi
#pragma unroll
            for (int mi = 0; mi < MF; mi++)
#pragma unroll
                for (int nf = 0; nf < 4; nf++)
                    mma16816(acc[mi][nf], ah[mi], bh[nf >> 1][nf & 1], bh[nf >> 1][(nf & 1) + 2]);
            // pass 1: Ahi * Blo
#pragma unroll
            for (int mi = 0; mi < MF; mi++)
#pragma unroll
                for (int nf = 0; nf < 4; nf++)
                    mma16816(acc[mi][nf], ah[mi], bl[nf >> 1][nf & 1], bl[nf >> 1][(nf & 1) + 2]);
            // pass 2: Alo * Bhi
#pragma unroll
            for (int mi = 0; mi < MF; mi++)
#pragma unroll
                for (int nf = 0; nf < 4; nf++)
                    mma16816(acc[mi][nf], al[mi], bh[nf >> 1][nf & 1], bh[nf >> 1][(nf & 1) + 2]);
        }
    }
    __syncthreads();   // protect stage buffers before epilogue reuse
}

// ---------------- xgates: writes transposed g_xg[t][batch][gate] ----------------
// BM=128, stage=64KB, S=3 -> 192KB smem
#define XG_SMEM (3 * (2 * 128 * 128 + 2 * 128 * 128))

__global__ __launch_bounds__(256, 1)
void xgates_mma_kernel() {
    extern __shared__ __align__(1024) char smem[];
    const uint32_t sbase = smem_u32(smem);
    const int bn = blockIdx.x, bm = blockIdx.y;
    const int tid = threadIdx.x, lane = tid & 31, wid = tid >> 5;
    const int wm = (wid >> 2) * 64, wn = (wid & 3) * 32;

    float acc[4][4][4];
#pragma unroll
    for (int i = 0; i < 4; i++)
#pragma unroll
        for (int j = 0; j < 4; j++)
#pragma unroll
            for (int k = 0; k < 4; k++) acc[i][j][k] = 0.0f;

    mma_mainloop<128, 4, 3>(g_x_hi, g_x_lo, g_Wih_hi, g_Wih_lo, DD,
                            bm * 128, bn * 128, sbase, acc);

#pragma unroll
    for (int mi = 0; mi < 4; mi++) {
#pragma unroll
        for (int nf = 0; nf < 4; nf++) {
            int m = bm * 128 + wm + mi * 16 + lane / 4;
            int n = bn * 128 + wn + nf * 8 + 2 * (lane & 3);
            float2 b2 = *reinterpret_cast<const float2*>(&g_bias_r[n]);
            int t0 = m % TT, b0 = m / TT;
            int m8 = m + 8;
            int t1 = m8 % TT, b1 = m8 / TT;
            *reinterpret_cast<float2*>(&g_xg[((size_t)t0 * NB + b0) * GG + n]) =
                make_float2(acc[mi][nf][0] + b2.x, acc[mi][nf][1] + b2.y);
            *reinterpret_cast<float2*>(&g_xg[((size_t)t1 * NB + b1) * GG + n]) =
                make_float2(acc[mi][nf][2] + b2.x, acc[mi][nf][3] + b2.y);
        }
    }
}

// ---------------- fused LSTM step ----------------
// BM=64: grid (32, 4) = 128 CTAs. stage=48KB, S=3 -> 144KB + 32KB xg = 176KB
#define STEP_BM      64
#define STEP_STAGE   (2 * STEP_BM * 128 + 2 * 128 * 128)
#define STEP_XG_OFF  (3 * STEP_STAGE)
#define STEP_SMEM    (STEP_XG_OFF + STEP_BM * 128 * 4)

__global__ __launch_bounds__(256, 1)
void lstm_step_mma(const bf16* __restrict__ h_hi, const bf16* __restrict__ h_lo,
                   bf16* __restrict__ hn_hi, bf16* __restrict__ hn_lo, int t) {
    extern __shared__ __align__(1024) char smem[];
    const uint32_t sbase = smem_u32(smem);
    const int bn = blockIdx.x, bm = blockIdx.y;
    const int tid = threadIdx.x, lane = tid & 31, wid = tid >> 5;
    const int wm = (wid >> 2) * 32, wn = (wid & 3) * 32;

    // prefetch this tile's x-gates [64 rows x 128 cols f32] (joins cp group 0)
    {
        const float* xgsrc = g_xg + ((size_t)t * NB + bm * STEP_BM) * GG + bn * 128;
#pragma unroll
        for (int s = 0; s < 8; s++) {
            int i = tid + s * 256;
            int row = i >> 5, j = i & 31;
            cp16(sbase + STEP_XG_OFF + row * 512 + j * 16, xgsrc + (size_t)row * GG + j * 4);
        }
    }

    float acc[2][4][4];
#pragma unroll
    for (int i = 0; i < 2; i++)
#pragma unroll
        for (int j = 0; j < 4; j++)
#pragma unroll
            for (int k = 0; k < 4; k++) acc[i][j][k] = 0.0f;

    mma_mainloop<STEP_BM, 2, 3>(h_hi, h_lo, g_Whh_hi, g_Whh_lo, HH,
                                bm * STEP_BM, bn * 128, sbase, acc);

    // stage gates in smem (pipeline buffers free after mainloop's trailing sync)
    float* gsm = reinterpret_cast<float*>(smem);
#pragma unroll
    for (int mi = 0; mi < 2; mi++) {
#pragma unroll
        for (int nf = 0; nf < 4; nf++) {
            int r0 = wm + mi * 16 + lane / 4;
            int col = wn + nf * 8 + 2 * (lane & 3);
            *reinterpret_cast<float2*>(&gsm[r0 * 128 + col]) =
                make_float2(acc[mi][nf][0], acc[mi][nf][1]);
            *reinterpret_cast<float2*>(&gsm[(r0 + 8) * 128 + col]) =
                make_float2(acc[mi][nf][2], acc[mi][nf][3]);
        }
    }
    __syncthreads();

    const float* xgsm = reinterpret_cast<const float*>(smem + STEP_XG_OFF);
#pragma unroll
    for (int it = 0; it < 8; it++) {
        int idx = it * 256 + tid;
        int m = idx >> 5, q = idx & 31;
        int mg = bm * STEP_BM + m;
        int qg = bn * 32 + q;
        float4 gv = *reinterpret_cast<const float4*>(&gsm[m * 128 + q * 4]);
        float4 xv = *reinterpret_cast<const float4*>(&xgsm[m * 128 + q * 4]);
        float a0 = gv.x + xv.x;
        float a1 = gv.y + xv.y;
        float a2 = gv.z + xv.z;
        float a3 = gv.w + xv.w;
        float ig = 1.0f / (1.0f + expf(-a0));
        float fg = 1.0f / (1.0f + expf(-a1));
        float gg = tanhf(a2);
        float og = 1.0f / (1.0f + expf(-a3));
        float cn = fg * g_cbuf[mg * HH + qg] + ig * gg;
        g_cbuf[mg * HH + qg] = cn;
        float hv = og * tanhf(cn);
        g_hlast[mg * HH + qg] = hv;
        bf16 hi = __float2bfloat16(hv);
        hn_hi[(size_t)mg * HH + qg] = hi;
        hn_lo[(size_t)mg * HH + qg] = __float2bfloat16(hv - __bfloat162float(hi));
    }
}

// ---------------- fp32 SIMT GEMM (head only) ----------------
#define EPI_BIAS 0
#define EPI_RELU 1
template <int BM, int BN, int BK, int TM, int TN, int EPI>
__global__ void gemm_bias_kernel(const float* __restrict__ A,
                                 const float* __restrict__ B,
                                 const float* __restrict__ bias,
                                 float* __restrict__ C,
                                 int M, int N, int K) {
    constexpr int NT = (BM * BN) / (TM * TN);
    __shared__ float As[BK][BM];
    __shared__ float Bs[BK][BN];
    const int tid = threadIdx.x;
    const int bn = blockIdx.x, bm = blockIdx.y;
    const int tx = tid % (BN / TN);
    const int ty = tid / (BN / TN);
    const float* Ab = A + (size_t)bm * BM * K;
    const float* Bb = B + (size_t)bn * BN * K;
    float acc[TM][TN];
#pragma unroll
    for (int i = 0; i < TM; i++)
#pragma unroll
        for (int j = 0; j < TN; j++) acc[i][j] = 0.0f;
    for (int k0 = 0; k0 < K; k0 += BK) {
        constexpr int A4 = BM * BK / 4;
        constexpr int B4 = BN * BK / 4;
#pragma unroll
        for (int i0 = 0; i0 < A4; i0 += NT) {
            int i = i0 + tid;
            int r = i / (BK / 4), c = (i % (BK / 4)) * 4;
            float4 v = *reinterpret_cast<const float4*>(Ab + (size_t)r * K + k0 + c);
            As[c + 0][r] = v.x; As[c + 1][r] = v.y; As[c + 2][r] = v.z; As[c + 3][r] = v.w;
        }
#pragma unroll
        for (int i0 = 0; i0 < B4; i0 += NT) {
            int i = i0 + tid;
            int r = i / (BK / 4), c = (i % (BK / 4)) * 4;
            float4 v = *reinterpret_cast<const float4*>(Bb + (size_t)r * K + k0 + c);
            Bs[c + 0][r] = v.x; Bs[c + 1][r] = v.y; Bs[c + 2][r] = v.z; Bs[c + 3][r] = v.w;
        }
        __syncthreads();
#pragma unroll
        for (int k = 0; k < BK; k++) {
            float ra[TM], rb[TN];
#pragma unroll
            for (int i = 0; i < TM; i += 4) {
                float4 v = *reinterpret_cast<const float4*>(&As[k][ty * TM + i]);
                ra[i] = v.x; ra[i + 1] = v.y; ra[i + 2] = v.z; ra[i + 3] = v.w;
            }
#pragma unroll
            for (int j = 0; j < TN; j += 4) {
                float4 v = *reinterpret_cast<const float4*>(&Bs[k][tx * TN + j]);
                rb[j] = v.x; rb[j + 1] = v.y; rb[j + 2] = v.z; rb[j + 3] = v.w;
            }
#pragma unroll
            for (int i = 0; i < TM; i++)
#pragma unroll
                for (int j = 0; j < TN; j++) acc[i][j] += ra[i] * rb[j];
        }
        __syncthreads();
    }
#pragma unroll
    for (int i = 0; i < TM; i++) {
        int m = bm * BM + ty * TM + i;
#pragma unroll
        for (int j = 0; j < TN; j++) {
            int n = bn * BN + tx * TN + j;
            float v = acc[i][j] + bias[n];
            if (EPI == EPI_RELU) v = fmaxf(v, 0.0f);
            C[(size_t)m * N + n] = v;
        }
    }
}

// ---------------- host ----------------
extern "C" void kernel_launch(void* const* d_in, const int* in_sizes, int n_in,
                              void* d_out, int out_size) {
    const float* x    = (const float*)d_in[0];
    const float* W_ih = (const float*)d_in[1];
    const float* W_hh = (const float*)d_in[2];
    const float* b_ih = (const float*)d_in[3];
    const float* b_hh = (const float*)d_in[4];
    const float* W1   = (const float*)d_in[5];
    const float* b1   = (const float*)d_in[6];
    const float* W2   = (const float*)d_in[7];
    const float* b2   = (const float*)d_in[8];
    float* out = (float*)d_out;

    float* p_hlast;
    bf16 *p_hhi[2], *p_hlo[2];
    cudaGetSymbolAddress((void**)&p_hlast, g_hlast);
    {
        bf16* base;
        cudaGetSymbolAddress((void**)&base, g_h_hi);
        p_hhi[0] = base; p_hhi[1] = base + NB * HH;
        cudaGetSymbolAddress((void**)&base, g_h_lo);
        p_hlo[0] = base; p_hlo[1] = base + NB * HH;
    }

    static int attr_set = 0;
    if (!attr_set) {
        cudaFuncSetAttribute(lstm_step_mma, cudaFuncAttributeMaxDynamicSharedMemorySize, STEP_SMEM);
        cudaFuncSetAttribute(xgates_mma_kernel, cudaFuncAttributeMaxDynamicSharedMemorySize, XG_SMEM);
        attr_set = 1;
    }

    // 1) reorder + hi/lo split weights and x; zero state
    prep_kernel<<<1024, 256>>>(x, W_ih, W_hh, b_ih, b_hh);

    // 2) x_gates via HMMA, written transposed [t][batch][gate]
    xgates_mma_kernel<<<dim3(GG / 128, (NB * TT) / 128), 256, XG_SMEM>>>();

    // 3) 128 recurrent steps via HMMA, fused cell update
    for (int t = 0; t < TT; t++) {
        int a = t & 1, b = (t + 1) & 1;
        lstm_step_mma<<<dim3(GG / 128, NB / STEP_BM), 256, STEP_SMEM>>>(
            p_hhi[a], p_hlo[a], p_hhi[b], p_hlo[b], t);
    }

    // 4) head (fp32 SIMT)
    float* pre_out = out + NB * OUTD;
    gemm_bias_kernel<64, 128, 16, 4, 8, EPI_RELU>
        <<<dim3(HH / 128, NB / 64), 256>>>(p_hlast, W1, b1, pre_out, NB, HH, HH);
    gemm_bias_kernel<64, 128, 16, 4, 8, EPI_BIAS>
        <<<dim3(OUTD / 128, NB / 64), 256>>>(pre_out, W2, b2, out, NB, OUTD, HH);
}

// round 8
// speedup vs baseline: 3.9102x; 1.0504x over previous
#include <cuda_runtime.h>
#include <cuda_bf16.h>
#include <math.h>
#include <stdint.h>

// Problem dims (fixed)
#define NB   256
#define TT   128
#define DD   512
#define HH   1024
#define GG   4096
#define OUTD 128

typedef __nv_bfloat16 bf16;

// ---------------- device scratch ----------------
__device__ bf16 g_Wih_hi[GG * DD];
__device__ bf16 g_Wih_lo[GG * DD];
__device__ bf16 g_Whh_hi[GG * HH];
__device__ bf16 g_Whh_lo[GG * HH];
__device__ bf16 g_x_hi[(size_t)NB * TT * DD];
__device__ bf16 g_x_lo[(size_t)NB * TT * DD];
__device__ float g_bias_r[GG];
__device__ float g_xg[(size_t)TT * NB * GG];   // [t][batch][gate]
__device__ bf16 g_h_hi[2][NB * HH];
__device__ bf16 g_h_lo[2][NB * HH];
__device__ float g_hlast[NB * HH];
__device__ float g_cbuf[NB * HH];

// ---------------- low-level helpers ----------------
__device__ __forceinline__ uint32_t smem_u32(const void* p) {
    uint32_t a;
    asm("{ .reg .u64 t; cvta.to.shared.u64 t, %1; cvt.u32.u64 %0, t; }" : "=r"(a) : "l"(p));
    return a;
}
__device__ __forceinline__ void cp16(uint32_t dst, const void* src) {
    asm volatile("cp.async.cg.shared.global [%0], [%1], 16;"
                 :: "r"(dst), "l"(__cvta_generic_to_global(src)) : "memory");
}
#define CP_COMMIT() asm volatile("cp.async.commit_group;" ::: "memory")
#define CP_WAIT(n)  asm volatile("cp.async.wait_group %0;" :: "n"(n) : "memory")

__device__ __forceinline__ void ldsm4(uint32_t* r, uint32_t addr) {
    asm volatile("ldmatrix.sync.aligned.m8n8.x4.shared.b16 {%0,%1,%2,%3}, [%4];"
                 : "=r"(r[0]), "=r"(r[1]), "=r"(r[2]), "=r"(r[3]) : "r"(addr));
}
__device__ __forceinline__ void mma16816(float* d, const uint32_t* a, uint32_t b0, uint32_t b1) {
    asm volatile(
        "mma.sync.aligned.m16n8k16.row.col.f32.bf16.bf16.f32 "
        "{%0,%1,%2,%3}, {%4,%5,%6,%7}, {%8,%9}, {%0,%1,%2,%3};"
        : "+f"(d[0]), "+f"(d[1]), "+f"(d[2]), "+f"(d[3])
        : "r"(a[0]), "r"(a[1]), "r"(a[2]), "r"(a[3]), "r"(b0), "r"(b1));
}

// tile rows = 64 bf16 = 128B = 8 x 16B chunks; 8-way XOR swizzle within the row
__device__ __forceinline__ uint32_t swz(int row, int j) {
    return (uint32_t)(row * 128 + ((j ^ (row & 7)) << 4));
}

// ---------------- prep ----------------
__global__ void prep_kernel(const float* __restrict__ x,
                            const float* __restrict__ Wih,
                            const float* __restrict__ Whh,
                            const float* __restrict__ bih,
                            const float* __restrict__ bhh) {
    int idx = blockIdx.x * blockDim.x + threadIdx.x;
    int stride = gridDim.x * blockDim.x;
    for (int i = idx; i < GG * DD; i += stride) {
        int rn = i / DD, d = i - rn * DD;
        int q = rn >> 2, p = rn & 3;
        float w = Wih[(p * HH + q) * DD + d];
        bf16 hi = __float2bfloat16(w);
        g_Wih_hi[i] = hi;
        g_Wih_lo[i] = __float2bfloat16(w - __bfloat162float(hi));
    }
    for (int i = idx; i < GG * HH; i += stride) {
        int rn = i / HH, d = i - rn * HH;
        int q = rn >> 2, p = rn & 3;
        float w = Whh[(p * HH + q) * HH + d];
        bf16 hi = __float2bfloat16(w);
        g_Whh_hi[i] = hi;
        g_Whh_lo[i] = __float2bfloat16(w - __bfloat162float(hi));
    }
    for (size_t i = idx; i < (size_t)NB * TT * DD; i += stride) {
        float v = x[i];
        bf16 hi = __float2bfloat16(v);
        g_x_hi[i] = hi;
        g_x_lo[i] = __float2bfloat16(v - __bfloat162float(hi));
    }
    for (int i = idx; i < GG; i += stride) {
        int q = i >> 2, p = i & 3;
        g_bias_r[i] = bih[p * HH + q] + bhh[p * HH + q];
    }
    for (int i = idx; i < NB * HH; i += stride) {
        g_h_hi[0][i] = __float2bfloat16(0.0f);
        g_h_lo[0][i] = __float2bfloat16(0.0f);
        g_cbuf[i] = 0.0f;
    }
}

// ---------------- combined-pass multistage HMMA mainloop (512 threads) ----------------
// Per K-chunk (BK=64) load Ahi, Alo, Bhi, Blo ONCE; 3 MMA passes reuse frags.
// 16 warps as 4(M) x 4(N); M-warp rows = 16*MF; warp tile (16*MF) x 32.
template <int BM, int MF, int S>
__device__ __forceinline__ void mma_mainloop(
    const bf16* __restrict__ Ahi, const bf16* __restrict__ Alo,
    const bf16* __restrict__ Bhi, const bf16* __restrict__ Blo,
    int K, int m0, int n0, uint32_t sbase, float acc[MF][4][4]) {
    constexpr int NT = 512;
    constexpr int ATILE = BM * 128;
    constexpr int BTILE = 128 * 128;
    constexpr int STAGE = 2 * ATILE + 2 * BTILE;
    const int tid = threadIdx.x;
    const int lane = tid & 31, wid = tid >> 5;
    const int wm = (wid >> 2) * (16 * MF);
    const int wn = (wid & 3) * 32;
    const int KC = K / 64;

    auto load_chunk = [&](int kc, int buf) {
        uint32_t base = sbase + buf * STAGE;
#pragma unroll
        for (int i0 = 0; i0 < BM * 8; i0 += NT) {
            int i = i0 + tid;
            int row = i >> 3, j = i & 7;
            size_t goff = (size_t)(m0 + row) * K + kc * 64 + j * 8;
            uint32_t so = swz(row, j);
            cp16(base + so, Ahi + goff);
            cp16(base + ATILE + so, Alo + goff);
        }
#pragma unroll
        for (int i0 = 0; i0 < 1024; i0 += NT) {
            int i = i0 + tid;
            int row = i >> 3, j = i & 7;
            size_t goff = (size_t)(n0 + row) * K + kc * 64 + j * 8;
            uint32_t so = swz(row, j);
            cp16(base + 2 * ATILE + so, Bhi + goff);
            cp16(base + 2 * ATILE + BTILE + so, Blo + goff);
        }
        CP_COMMIT();
    };

    // prologue: stages 0..S-2 (caller's earlier cp.async joins group 0)
#pragma unroll
    for (int s = 0; s < S - 1; s++) load_chunk(s, s);

    int cbuf = 0;
    int lbuf = (S - 1) % S;
    for (int ci = 0; ci < KC; ci++) {
        CP_WAIT(S - 2);
        __syncthreads();
        if (ci + S - 1 < KC) load_chunk(ci + S - 1, lbuf);
        else CP_COMMIT();
        lbuf = (lbuf + 1 == S) ? 0 : lbuf + 1;
        uint32_t sAh = sbase + cbuf * STAGE;
        uint32_t sAl = sAh + ATILE;
        uint32_t sBh = sAh + 2 * ATILE;
        uint32_t sBl = sBh + BTILE;
        cbuf = (cbuf + 1 == S) ? 0 : cbuf + 1;
#pragma unroll
        for (int ks = 0; ks < 4; ks++) {
            uint32_t ah[MF][4], al[MF][4], bh[2][4], bl[2][4];
            const int j = ks * 2 + (lane >> 4);
#pragma unroll
            for (int mi = 0; mi < MF; mi++) {
                int row = wm + mi * 16 + (lane & 15);
                uint32_t so = swz(row, j);
                ldsm4(ah[mi], sAh + so);
                ldsm4(al[mi], sAl + so);
            }
#pragma unroll
            for (int bi = 0; bi < 2; bi++) {
                int row = wn + bi * 16 + (lane & 15);
                uint32_t so = swz(row, j);
                ldsm4(bh[bi], sBh + so);
                ldsm4(bl[bi], sBl + so);
            }
            // pass 0: Ahi * Bhi
#pragma unroll
            for (int mi = 0; mi < MF; mi++)
#pragma unroll
                for (int nf = 0; nf < 4; nf++)
                    mma16816(acc[mi][nf], ah[mi], bh[nf >> 1][nf & 1], bh[nf >> 1][(nf & 1) + 2]);
            // pass 1: Ahi * Blo
#pragma unroll
            for (int mi = 0; mi < MF; mi++)
#pragma unroll
                for (int nf = 0; nf < 4; nf++)
                    mma16816(acc[mi][nf], ah[mi], bl[nf >> 1][nf & 1], bl[nf >> 1][(nf & 1) + 2]);
            // pass 2: Alo * Bhi
#pragma unroll
            for (int mi = 0; mi < MF; mi++)
#pragma unroll
                for (int nf = 0; nf < 4; nf++)
                    mma16816(acc[mi][nf], al[mi], bh[nf >> 1][nf & 1], bh[nf >> 1][(nf & 1) + 2]);
        }
    }
    __syncthreads();   // protect stage buffers before epilogue reuse
}

// ---------------- xgates: writes transposed g_xg[t][batch][gate] ----------------
// BM=128, MF=2 (warp tile 32x32), stage=64KB, S=3 -> 192KB smem, 512 threads
#define XG_SMEM (3 * (2 * 128 * 128 + 2 * 128 * 128))

__global__ __launch_bounds__(512, 1)
void xgates_mma_kernel() {
    extern __shared__ __align__(1024) char smem[];
    const uint32_t sbase = smem_u32(smem);
    const int bn = blockIdx.x, bm = blockIdx.y;
    const int tid = threadIdx.x, lane = tid & 31, wid = tid >> 5;
    const int wm = (wid >> 2) * 32, wn = (wid & 3) * 32;

    float acc[2][4][4];
#pragma unroll
    for (int i = 0; i < 2; i++)
#pragma unroll
        for (int j = 0; j < 4; j++)
#pragma unroll
            for (int k = 0; k < 4; k++) acc[i][j][k] = 0.0f;

    mma_mainloop<128, 2, 3>(g_x_hi, g_x_lo, g_Wih_hi, g_Wih_lo, DD,
                            bm * 128, bn * 128, sbase, acc);

#pragma unroll
    for (int mi = 0; mi < 2; mi++) {
#pragma unroll
        for (int nf = 0; nf < 4; nf++) {
            int m = bm * 128 + wm + mi * 16 + lane / 4;
            int n = bn * 128 + wn + nf * 8 + 2 * (lane & 3);
            float2 b2 = *reinterpret_cast<const float2*>(&g_bias_r[n]);
            int t0 = m % TT, b0 = m / TT;
            int m8 = m + 8;
            int t1 = m8 % TT, b1 = m8 / TT;
            *reinterpret_cast<float2*>(&g_xg[((size_t)t0 * NB + b0) * GG + n]) =
                make_float2(acc[mi][nf][0] + b2.x, acc[mi][nf][1] + b2.y);
            *reinterpret_cast<float2*>(&g_xg[((size_t)t1 * NB + b1) * GG + n]) =
                make_float2(acc[mi][nf][2] + b2.x, acc[mi][nf][3] + b2.y);
        }
    }
}

// ---------------- fused LSTM step ----------------
// BM=64, MF=1 (warp tile 16x32): grid (32, 4) = 128 CTAs, 512 threads.
// stage=48KB, S=3 -> 144KB + 32KB xg = 176KB
#define STEP_BM      64
#define STEP_STAGE   (2 * STEP_BM * 128 + 2 * 128 * 128)
#define STEP_XG_OFF  (3 * STEP_STAGE)
#define STEP_SMEM    (STEP_XG_OFF + STEP_BM * 128 * 4)

__global__ __launch_bounds__(512, 1)
void lstm_step_mma(const bf16* __restrict__ h_hi, const bf16* __restrict__ h_lo,
                   bf16* __restrict__ hn_hi, bf16* __restrict__ hn_lo, int t) {
    extern __shared__ __align__(1024) char smem[];
    const uint32_t sbase = smem_u32(smem);
    const int bn = blockIdx.x, bm = blockIdx.y;
    const int tid = threadIdx.x, lane = tid & 31, wid = tid >> 5;
    const int wm = (wid >> 2) * 16, wn = (wid & 3) * 32;

    // prefetch this tile's x-gates [64 rows x 128 cols f32] (joins cp group 0)
    {
        const float* xgsrc = g_xg + ((size_t)t * NB + bm * STEP_BM) * GG + bn * 128;
#pragma unroll
        for (int s = 0; s < 4; s++) {
            int i = tid + s * 512;
            int row = i >> 5, j = i & 31;
            cp16(sbase + STEP_XG_OFF + row * 512 + j * 16, xgsrc + (size_t)row * GG + j * 4);
        }
    }

    float acc[1][4][4];
#pragma unroll
    for (int j = 0; j < 4; j++)
#pragma unroll
        for (int k = 0; k < 4; k++) acc[0][j][k] = 0.0f;

    mma_mainloop<STEP_BM, 1, 3>(h_hi, h_lo, g_Whh_hi, g_Whh_lo, HH,
                                bm * STEP_BM, bn * 128, sbase, acc);

    // stage gates in smem (pipeline buffers free after mainloop's trailing sync)
    float* gsm = reinterpret_cast<float*>(smem);
#pragma unroll
    for (int nf = 0; nf < 4; nf++) {
        int r0 = wm + lane / 4;
        int col = wn + nf * 8 + 2 * (lane & 3);
        *reinterpret_cast<float2*>(&gsm[r0 * 128 + col]) =
            make_float2(acc[0][nf][0], acc[0][nf][1]);
        *reinterpret_cast<float2*>(&gsm[(r0 + 8) * 128 + col]) =
            make_float2(acc[0][nf][2], acc[0][nf][3]);
    }
    __syncthreads();

    const float* xgsm = reinterpret_cast<const float*>(smem + STEP_XG_OFF);
#pragma unroll
    for (int it = 0; it < 4; it++) {
        int idx = it * 512 + tid;
        int m = idx >> 5, q = idx & 31;
        int mg = bm * STEP_BM + m;
        int qg = bn * 32 + q;
        float4 gv = *reinterpret_cast<const float4*>(&gsm[m * 128 + q * 4]);
        float4 xv = *reinterpret_cast<const float4*>(&xgsm[m * 128 + q * 4]);
        float a0 = gv.x + xv.x;
        float a1 = gv.y + xv.y;
        float a2 = gv.z + xv.z;
        float a3 = gv.w + xv.w;
        float ig = 1.0f / (1.0f + expf(-a0));
        float fg = 1.0f / (1.0f + expf(-a1));
        float gg = tanhf(a2);
        float og = 1.0f / (1.0f + expf(-a3));
        float cn = fg * g_cbuf[mg * HH + qg] + ig * gg;
        g_cbuf[mg * HH + qg] = cn;
        float hv = og * tanhf(cn);
        g_hlast[mg * HH + qg] = hv;
        bf16 hi = __float2bfloat16(hv);
        hn_hi[(size_t)mg * HH + qg] = hi;
        hn_lo[(size_t)mg * HH + qg] = __float2bfloat16(hv - __bfloat162float(hi));
    }
}

// ---------------- fp32 SIMT GEMM (head only) ----------------
#define EPI_BIAS 0
#define EPI_RELU 1
template <int BM, int BN, int BK, int TM, int TN, int EPI>
__global__ void gemm_bias_kernel(const float* __restrict__ A,
                                 const float* __restrict__ B,
                                 const float* __restrict__ bias,
                                 float* __restrict__ C,
                                 int M, int N, int K) {
    constexpr int NT = (BM * BN) / (TM * TN);
    __shared__ float As[BK][BM];
    __shared__ float Bs[BK][BN];
    const int tid = threadIdx.x;
    const int bn = blockIdx.x, bm = blockIdx.y;
    const int tx = tid % (BN / TN);
    const int ty = tid / (BN / TN);
    const float* Ab = A + (size_t)bm * BM * K;
    const float* Bb = B + (size_t)bn * BN * K;
    float acc[TM][TN];
#pragma unroll
    for (int i = 0; i < TM; i++)
#pragma unroll
        for (int j = 0; j < TN; j++) acc[i][j] = 0.0f;
    for (int k0 = 0; k0 < K; k0 += BK) {
        constexpr int A4 = BM * BK / 4;
        constexpr int B4 = BN * BK / 4;
#pragma unroll
        for (int i0 = 0; i0 < A4; i0 += NT) {
            int i = i0 + tid;
            int r = i / (BK / 4), c = (i % (BK / 4)) * 4;
            float4 v = *reinterpret_cast<const float4*>(Ab + (size_t)r * K + k0 + c);
            As[c + 0][r] = v.x; As[c + 1][r] = v.y; As[c + 2][r] = v.z; As[c + 3][r] = v.w;
        }
#pragma unroll
        for (int i0 = 0; i0 < B4; i0 += NT) {
            int i = i0 + tid;
            int r = i / (BK / 4), c = (i % (BK / 4)) * 4;
            float4 v = *reinterpret_cast<const float4*>(Bb + (size_t)r * K + k0 + c);
            Bs[c + 0][r] = v.x; Bs[c + 1][r] = v.y; Bs[c + 2][r] = v.z; Bs[c + 3][r] = v.w;
        }
        __syncthreads();
#pragma unroll
        for (int k = 0; k < BK; k++) {
            float ra[TM], rb[TN];
#pragma unroll
            for (int i = 0; i < TM; i += 4) {
                float4 v = *reinterpret_cast<const float4*>(&As[k][ty * TM + i]);
                ra[i] = v.x; ra[i + 1] = v.y; ra[i + 2] = v.z; ra[i + 3] = v.w;
            }
#pragma unroll
            for (int j = 0; j < TN; j += 4) {
                float4 v = *reinterpret_cast<const float4*>(&Bs[k][tx * TN + j]);
                rb[j] = v.x; rb[j + 1] = v.y; rb[j + 2] = v.z; rb[j + 3] = v.w;
            }
#pragma unroll
            for (int i = 0; i < TM; i++)
#pragma unroll
                for (int j = 0; j < TN; j++) acc[i][j] += ra[i] * rb[j];
        }
        __syncthreads();
    }
#pragma unroll
    for (int i = 0; i < TM; i++) {
        int m = bm * BM + ty * TM + i;
#pragma unroll
        for (int j = 0; j < TN; j++) {
            int n = bn * BN + tx * TN + j;
            float v = acc[i][j] + bias[n];
            if (EPI == EPI_RELU) v = fmaxf(v, 0.0f);
            C[(size_t)m * N + n] = v;
        }
    }
}

// ---------------- host ----------------
extern "C" void kernel_launch(void* const* d_in, const int* in_sizes, int n_in,
                              void* d_out, int out_size) {
    const float* x    = (const float*)d_in[0];
    const float* W_ih = (const float*)d_in[1];
    const float* W_hh = (const float*)d_in[2];
    const float* b_ih = (const float*)d_in[3];
    const float* b_hh = (const float*)d_in[4];
    const float* W1   = (const float*)d_in[5];
    const float* b1   = (const float*)d_in[6];
    const float* W2   = (const float*)d_in[7];
    const float* b2   = (const float*)d_in[8];
    float* out = (float*)d_out;

    float* p_hlast;
    bf16 *p_hhi[2], *p_hlo[2];
    cudaGetSymbolAddress((void**)&p_hlast, g_hlast);
    {
        bf16* base;
        cudaGetSymbolAddress((void**)&base, g_h_hi);
        p_hhi[0] = base; p_hhi[1] = base + NB * HH;
        cudaGetSymbolAddress((void**)&base, g_h_lo);
        p_hlo[0] = base; p_hlo[1] = base + NB * HH;
    }

    static int attr_set = 0;
    if (!attr_set) {
        cudaFuncSetAttribute(lstm_step_mma, cudaFuncAttributeMaxDynamicSharedMemorySize, STEP_SMEM);
        cudaFuncSetAttribute(xgates_mma_kernel, cudaFuncAttributeMaxDynamicSharedMemorySize, XG_SMEM);
        attr_set = 1;
    }

    // 1) reorder + hi/lo split weights and x; zero state
    prep_kernel<<<1024, 256>>>(x, W_ih, W_hh, b_ih, b_hh);

    // 2) x_gates via HMMA, written transposed [t][batch][gate]
    xgates_mma_kernel<<<dim3(GG / 128, (NB * TT) / 128), 512, XG_SMEM>>>();

    // 3) 128 recurrent steps via HMMA, fused cell update
    for (int t = 0; t < TT; t++) {
        int a = t & 1, b = (t + 1) & 1;
        lstm_step_mma<<<dim3(GG / 128, NB / STEP_BM), 512, STEP_SMEM>>>(
            p_hhi[a], p_hlo[a], p_hhi[b], p_hlo[b], t);
    }

    // 4) head (fp32 SIMT)
    float* pre_out = out + NB * OUTD;
    gemm_bias_kernel<64, 128, 16, 4, 8, EPI_RELU>
        <<<dim3(HH / 128, NB / 64), 256>>>(p_hlast, W1, b1, pre_out, NB, HH, HH);
    gemm_bias_kernel<64, 128, 16, 4, 8, EPI_BIAS>
        <<<dim3(OUTD / 128, NB / 64), 256>>>(pre_out, W2, b2, out, NB, OUTD, HH);
}